// round 1
// baseline (speedup 1.0000x reference)
#include <cuda_runtime.h>
#include <cuda_bf16.h>
#include <math.h>

// ---------------------------------------------------------------------------
// POMO decoder, fp32 baseline.
// Shapes: B=64, N=500, E=128, H=8, D=16 (H*D=128)
// Stages:
//   0) mask -> bitmask (1 = keep)
//   1) q = enc_first@Wqf^T + enc_last@Wql^T   -> [B,H,N,D]
//      k = enc_nodes@Wk^T, v = enc_nodes@Wv^T -> [B,H,N,D]
//   2) masked MHA (no-max softmax; mask as multiplicative bit) -> att [B,N,128]
//   3) mh = att@Wc^T + bc                      -> [B,N,128]
//   4) pointer: s = mh@enc^T/sqrt(128); 10*tanh(s)+mask; softmax -> out [B,N,N]
// ---------------------------------------------------------------------------

#define Bb 64
#define Nn 500
#define Ee 128
#define Hh 8
#define Dd 16

__device__ float g_q[Bb * Hh * Nn * Dd];
__device__ float g_k[Bb * Hh * Nn * Dd];
__device__ float g_v[Bb * Hh * Nn * Dd];
__device__ float g_att[Bb * Nn * (Hh * Dd)];
__device__ float g_mh[Bb * Nn * Ee];
__device__ unsigned g_maskbits[Bb * Nn * 16];

__device__ __forceinline__ float dot4(const float4& a, const float4& b) {
    return a.x * b.x + a.y * b.y + a.z * b.z + a.w * b.w;
}
__device__ __forceinline__ void fma4(float4& a, float p, const float4& v) {
    a.x += p * v.x; a.y += p * v.y; a.z += p * v.z; a.w += p * v.w;
}

// ---------------------------------------------------------------------------
// Stage 0: mask [B,N,N] (0 or -1e9) -> bitmask, 1 bit per g; bits >= N are 0.
// One warp per (b,n) row.
// ---------------------------------------------------------------------------
__global__ void maskbits_kernel(const float* __restrict__ mask,
                                unsigned* __restrict__ bits) {
    int warp = (blockIdx.x * blockDim.x + threadIdx.x) >> 5;
    int lane = threadIdx.x & 31;
    if (warp >= Bb * Nn) return;
    const float* row = mask + (size_t)warp * Nn;
    unsigned* brow = bits + (size_t)warp * 16;
    #pragma unroll
    for (int w = 0; w < 16; ++w) {
        int g = w * 32 + lane;
        float v = (g < Nn) ? row[g] : -1e9f;
        unsigned bal = __ballot_sync(0xffffffffu, v > -1.0f);
        if (lane == 0) brow[w] = bal;
    }
}

// ---------------------------------------------------------------------------
// Generic 128-wide projection: C[m,f] = sum_e A0[m,e]*W0[f,e] (+ A1*W1) (+ bias)
// Tile: 64 rows x 128 cols, K=128 full. 256 threads: ty=t/32 (8 rows each,
// broadcast X loads), tx=t%32 (4 cols each via float4, conflict-free).
// headsLayout: write out[((b*H+h)*N+n)*D+d] with h=f/16, d=f%16.
// smem: Xs[64][128] + Wt[128][128] (transposed) = 96 KB dynamic.
// ---------------------------------------------------------------------------
__global__ void proj_kernel(const float* __restrict__ A0,
                            const float* __restrict__ W0,
                            const float* __restrict__ A1,
                            const float* __restrict__ W1,
                            const float* __restrict__ bias,
                            float* __restrict__ out,
                            int headsLayout) {
    extern __shared__ float sh[];
    float* Xs = sh;                 // [64][128]
    float* Wt = sh + 64 * 128;      // [128][128], Wt[e][f] = W[f][e]

    const int t  = threadIdx.x;
    const int ty = t >> 5;          // 0..7
    const int tx = t & 31;          // 0..31
    const int m0 = blockIdx.x * 64;

    float acc[8][4];
    #pragma unroll
    for (int i = 0; i < 8; ++i)
        acc[i][0] = acc[i][1] = acc[i][2] = acc[i][3] = 0.f;

    const int npass = (A1 != nullptr) ? 2 : 1;
    for (int pass = 0; pass < npass; ++pass) {
        const float* A = pass ? A1 : A0;
        const float* W = pass ? W1 : W0;
        if (pass) __syncthreads();
        // Xs: contiguous copy (coalesced, conflict-free)
        #pragma unroll 4
        for (int i = t; i < 64 * 128; i += 256)
            Xs[i] = A[(size_t)m0 * 128 + i];
        // Wt: transpose (global strided but L2-hot; smem writes conflict-free)
        #pragma unroll 4
        for (int i = t; i < 128 * 128; i += 256) {
            int e = i >> 7, f = i & 127;
            Wt[e * 128 + f] = W[f * 128 + e];
        }
        __syncthreads();
        #pragma unroll 2
        for (int e = 0; e < 128; ++e) {
            float4 w = *(const float4*)(Wt + e * 128 + tx * 4);
            #pragma unroll
            for (int i = 0; i < 8; ++i) {
                float x = Xs[(ty * 8 + i) * 128 + e];
                acc[i][0] += x * w.x; acc[i][1] += x * w.y;
                acc[i][2] += x * w.z; acc[i][3] += x * w.w;
            }
        }
    }

    const int f = tx * 4;
    float4 bv = make_float4(0.f, 0.f, 0.f, 0.f);
    if (bias) bv = *(const float4*)(bias + f);
    #pragma unroll
    for (int i = 0; i < 8; ++i) {
        int m = m0 + ty * 8 + i;
        float4 r;
        r.x = acc[i][0] + bv.x; r.y = acc[i][1] + bv.y;
        r.z = acc[i][2] + bv.z; r.w = acc[i][3] + bv.w;
        if (headsLayout) {
            int b = m / Nn, n = m % Nn;
            int h = f >> 4, d = f & 15;
            *(float4*)(out + (((size_t)(b * Hh + h) * Nn + n) * Dd + d)) = r;
        } else {
            *(float4*)(out + (size_t)m * 128 + f) = r;
        }
    }
}

// ---------------------------------------------------------------------------
// Stage 2: attention. One block per (b,h); 256 threads, 2 rows/thread.
// K,V staged in smem (padded to 512 rows of zeros). No-max softmax;
// mask applied as multiply by bit. smem = 2*512*16*4 = 64 KB.
// ---------------------------------------------------------------------------
__global__ void attn_kernel(const unsigned* __restrict__ maskbits,
                            float* __restrict__ outg) {
    extern __shared__ float sh[];
    float* Ks = sh;               // [512][16]
    float* Vs = sh + 512 * 16;

    const int t  = threadIdx.x;
    const int bh = blockIdx.x;
    const int b  = bh >> 3;
    const int h  = bh & 7;

    const float* kp = g_k + (size_t)bh * Nn * Dd;
    const float* vp = g_v + (size_t)bh * Nn * Dd;
    #pragma unroll 4
    for (int i = t; i < 512 * 16; i += 256) {
        Ks[i] = (i < Nn * Dd) ? kp[i] : 0.f;
        Vs[i] = (i < Nn * Dd) ? vp[i] : 0.f;
    }
    __syncthreads();

    const int  r0   = t;                 // < 500 always
    const int  r1   = t + 256;
    const bool has1 = (r1 < Nn);
    const int  r1c  = has1 ? r1 : 0;

    float4 q0[4], q1[4];
    {
        const float4* qp0 = (const float4*)(g_q + ((size_t)bh * Nn + r0) * Dd);
        const float4* qp1 = (const float4*)(g_q + ((size_t)bh * Nn + r1c) * Dd);
        #pragma unroll
        for (int j = 0; j < 4; ++j) { q0[j] = qp0[j]; q1[j] = qp1[j]; }
    }
    const unsigned* mb0 = maskbits + ((size_t)b * Nn + r0) * 16;
    const unsigned* mb1 = maskbits + ((size_t)b * Nn + r1c) * 16;

    float4 a0[4], a1[4];
    #pragma unroll
    for (int j = 0; j < 4; ++j) {
        a0[j] = make_float4(0.f, 0.f, 0.f, 0.f);
        a1[j] = make_float4(0.f, 0.f, 0.f, 0.f);
    }
    float l0 = 0.f, l1 = 0.f;

    const float4* Ks4 = (const float4*)Ks;
    const float4* Vs4 = (const float4*)Vs;

    for (int w = 0; w < 16; ++w) {
        unsigned bits0 = mb0[w];
        unsigned bits1 = mb1[w];
        int gbase = w * 32;
        #pragma unroll 8
        for (int j = 0; j < 32; ++j) {
            int g = gbase + j;
            float4 k0 = Ks4[g * 4 + 0], k1 = Ks4[g * 4 + 1];
            float4 k2 = Ks4[g * 4 + 2], k3 = Ks4[g * 4 + 3];
            float s0 = dot4(q0[0], k0) + dot4(q0[1], k1) +
                       dot4(q0[2], k2) + dot4(q0[3], k3);
            float s1 = dot4(q1[0], k0) + dot4(q1[1], k1) +
                       dot4(q1[2], k2) + dot4(q1[3], k3);
            float sel0 = (float)((bits0 >> j) & 1u);
            float sel1 = (float)((bits1 >> j) & 1u);
            float p0 = __expf(s0 * 0.25f) * sel0;
            float p1 = __expf(s1 * 0.25f) * sel1;
            l0 += p0; l1 += p1;
            float4 v0 = Vs4[g * 4 + 0], v1 = Vs4[g * 4 + 1];
            float4 v2 = Vs4[g * 4 + 2], v3 = Vs4[g * 4 + 3];
            fma4(a0[0], p0, v0); fma4(a0[1], p0, v1);
            fma4(a0[2], p0, v2); fma4(a0[3], p0, v3);
            fma4(a1[0], p1, v0); fma4(a1[1], p1, v1);
            fma4(a1[2], p1, v2); fma4(a1[3], p1, v3);
        }
    }

    {
        float inv0 = 1.0f / l0;
        float4* o0 = (float4*)(g_att + ((size_t)b * Nn + r0) * 128 + h * Dd);
        #pragma unroll
        for (int j = 0; j < 4; ++j) {
            float4 r = a0[j];
            r.x *= inv0; r.y *= inv0; r.z *= inv0; r.w *= inv0;
            o0[j] = r;
        }
    }
    if (has1) {
        float inv1 = 1.0f / l1;
        float4* o1 = (float4*)(g_att + ((size_t)b * Nn + r1) * 128 + h * Dd);
        #pragma unroll
        for (int j = 0; j < 4; ++j) {
            float4 r = a1[j];
            r.x *= inv1; r.y *= inv1; r.z *= inv1; r.w *= inv1;
            o1[j] = r;
        }
    }
    // silence unused warning for outg (kept for signature stability)
    (void)outg;
}

// ---------------------------------------------------------------------------
// Stage 4: pointer attention + softmax.
// Block = (b, 16-row tile). g processed in 4 tiles of 128 cols.
// s = 10*tanh(mh.enc/sqrt(128)) + mask; p=exp(s); row-normalize from smem.
// smem: Ms[16][128] + Est[128][132] + Ps[16][500] + rowsum[16] = ~105 KB.
// ---------------------------------------------------------------------------
#define RSQRT128 0.08838834764831845f

__global__ void pointer_kernel(const float* __restrict__ enc,
                               const float* __restrict__ mask,
                               float* __restrict__ out) {
    extern __shared__ float sh[];
    float* Ms     = sh;                       // [16][128]
    float* Est    = sh + 16 * 128;            // [128][132] (Est[e][c]=enc[g0+c][e])
    float* Ps     = Est + 128 * 132;          // [16][500]
    float* rowsum = Ps + 16 * Nn;             // [16]

    const int t  = threadIdx.x;
    const int ty = t >> 5;        // 0..7 -> local rows ty*2, ty*2+1
    const int tx = t & 31;        // cols tx*4
    const int b  = blockIdx.y;
    const int n0 = blockIdx.x * 16;

    #pragma unroll 2
    for (int i = t; i < 16 * 128; i += 256) {
        int r = i >> 7;
        int n = n0 + r;
        Ms[i] = (n < Nn) ? g_mh[((size_t)b * Nn + n) * 128 + (i & 127)] : 0.f;
    }
    if (t < 16) rowsum[t] = 0.f;

    const int rg0 = n0 + ty * 2;
    const int rg1 = rg0 + 1;
    const int mr0 = (rg0 < Nn) ? rg0 : Nn - 1;
    const int mr1 = (rg1 < Nn) ? rg1 : Nn - 1;
    float lsum0 = 0.f, lsum1 = 0.f;

    for (int gt = 0; gt < 4; ++gt) {
        const int gbase = gt * 128;
        __syncthreads();
        // transpose-load enc tile (zero-pad g >= N)
        #pragma unroll 4
        for (int i = t; i < 128 * 128; i += 256) {
            int c = i >> 7, e = i & 127;
            int g = gbase + c;
            Est[e * 132 + c] =
                (g < Nn) ? enc[((size_t)b * Nn + g) * 128 + e] : 0.f;
        }
        __syncthreads();

        float acc0[4] = {0.f, 0.f, 0.f, 0.f};
        float acc1[4] = {0.f, 0.f, 0.f, 0.f};
        const float* m0p = Ms + (ty * 2) * 128;
        const float* m1p = Ms + (ty * 2 + 1) * 128;
        #pragma unroll 4
        for (int e = 0; e < 128; ++e) {
            float4 wv = *(const float4*)(Est + e * 132 + tx * 4);
            float x0 = m0p[e], x1 = m1p[e];
            acc0[0] += x0 * wv.x; acc0[1] += x0 * wv.y;
            acc0[2] += x0 * wv.z; acc0[3] += x0 * wv.w;
            acc1[0] += x1 * wv.x; acc1[1] += x1 * wv.y;
            acc1[2] += x1 * wv.z; acc1[3] += x1 * wv.w;
        }

        const int g = gbase + tx * 4;
        if (g < Nn) {
            const float4 mk0 = *(const float4*)(mask + ((size_t)b * Nn + mr0) * Nn + g);
            const float4 mk1 = *(const float4*)(mask + ((size_t)b * Nn + mr1) * Nn + g);
            float4 p0, p1;
            p0.x = __expf(10.f * tanhf(acc0[0] * RSQRT128) + mk0.x);
            p0.y = __expf(10.f * tanhf(acc0[1] * RSQRT128) + mk0.y);
            p0.z = __expf(10.f * tanhf(acc0[2] * RSQRT128) + mk0.z);
            p0.w = __expf(10.f * tanhf(acc0[3] * RSQRT128) + mk0.w);
            p1.x = __expf(10.f * tanhf(acc1[0] * RSQRT128) + mk1.x);
            p1.y = __expf(10.f * tanhf(acc1[1] * RSQRT128) + mk1.y);
            p1.z = __expf(10.f * tanhf(acc1[2] * RSQRT128) + mk1.z);
            p1.w = __expf(10.f * tanhf(acc1[3] * RSQRT128) + mk1.w);
            lsum0 += p0.x + p0.y + p0.z + p0.w;
            lsum1 += p1.x + p1.y + p1.z + p1.w;
            *(float4*)(Ps + (size_t)(ty * 2) * Nn + g)     = p0;
            *(float4*)(Ps + (size_t)(ty * 2 + 1) * Nn + g) = p1;
        }
    }

    atomicAdd(&rowsum[ty * 2], lsum0);
    atomicAdd(&rowsum[ty * 2 + 1], lsum1);
    __syncthreads();
    if (t < 16) rowsum[t] = 1.0f / rowsum[t];
    __syncthreads();

    #pragma unroll 2
    for (int i = t; i < 16 * Nn; i += 256) {
        int r = i / Nn, g = i % Nn;
        int n = n0 + r;
        if (n < Nn)
            out[((size_t)b * Nn + n) * Nn + g] = Ps[i] * rowsum[r];
    }
}

// ---------------------------------------------------------------------------
// Launch
// ---------------------------------------------------------------------------
extern "C" void kernel_launch(void* const* d_in, const int* in_sizes, int n_in,
                              void* d_out, int out_size) {
    const float* enc_nodes = (const float*)d_in[0];
    const float* enc_first = (const float*)d_in[1];
    const float* enc_last  = (const float*)d_in[2];
    const float* mask      = (const float*)d_in[3];
    const float* Wq_first  = (const float*)d_in[4];
    const float* Wq_last   = (const float*)d_in[5];
    const float* Wk        = (const float*)d_in[6];
    const float* Wv        = (const float*)d_in[7];
    const float* Wc        = (const float*)d_in[8];
    const float* bc        = (const float*)d_in[9];
    float* out = (float*)d_out;

    void *pq, *pk, *pv, *patt, *pmh, *pbits;
    cudaGetSymbolAddress(&pq, g_q);
    cudaGetSymbolAddress(&pk, g_k);
    cudaGetSymbolAddress(&pv, g_v);
    cudaGetSymbolAddress(&patt, g_att);
    cudaGetSymbolAddress(&pmh, g_mh);
    cudaGetSymbolAddress(&pbits, g_maskbits);

    const int PROJ_SMEM = (64 * 128 + 128 * 128) * 4;              // 98304
    const int ATTN_SMEM = 2 * 512 * 16 * 4;                         // 65536
    const int PTR_SMEM  = (16 * 128 + 128 * 132 + 16 * Nn + 16) * 4;// 107840
    cudaFuncSetAttribute(proj_kernel,
        cudaFuncAttributeMaxDynamicSharedMemorySize, PROJ_SMEM);
    cudaFuncSetAttribute(attn_kernel,
        cudaFuncAttributeMaxDynamicSharedMemorySize, ATTN_SMEM);
    cudaFuncSetAttribute(pointer_kernel,
        cudaFuncAttributeMaxDynamicSharedMemorySize, PTR_SMEM);

    // 0) bitmask
    maskbits_kernel<<<(Bb * Nn + 7) / 8, 256>>>(mask, (unsigned*)pbits);
    // 1) projections (32000 rows / 64 = 500 blocks)
    proj_kernel<<<500, 256, PROJ_SMEM>>>(enc_first, Wq_first, enc_last, Wq_last,
                                         nullptr, (float*)pq, 1);
    proj_kernel<<<500, 256, PROJ_SMEM>>>(enc_nodes, Wk, nullptr, nullptr,
                                         nullptr, (float*)pk, 1);
    proj_kernel<<<500, 256, PROJ_SMEM>>>(enc_nodes, Wv, nullptr, nullptr,
                                         nullptr, (float*)pv, 1);
    // 2) attention (one block per (b,h))
    attn_kernel<<<Bb * Hh, 256, ATTN_SMEM>>>((const unsigned*)pbits,
                                             (float*)patt);
    // 3) combine
    proj_kernel<<<500, 256, PROJ_SMEM>>>((const float*)patt, Wc, nullptr,
                                         nullptr, bc, (float*)pmh, 0);
    // 4) pointer attention + softmax
    dim3 pgrid((Nn + 15) / 16, Bb);
    pointer_kernel<<<pgrid, 256, PTR_SMEM>>>(enc_nodes, mask, out);

    (void)in_sizes; (void)n_in; (void)out_size;
}

// round 2
// speedup vs baseline: 2.0069x; 2.0069x over previous
#include <cuda_runtime.h>
#include <math.h>

// ---------------------------------------------------------------------------
// POMO decoder v2 — fp32x2 packed-FMA pipeline.
// B=64, N=500, E=128, H=8, D=16
// Launches:
//   A) stageA   : maskbits + q/k/v projections (fused, 1750 blocks)
//   B) attn     : masked MHA, no-max softmax, f32x2 over d (1024 blocks)
//   C) combine  : att @ Wc^T + bc (500 blocks)
//   D) pointer  : 10*tanh(mh.enc/sqrt128), bit-gated exp, in-block normalize
// ---------------------------------------------------------------------------

#define Bb 64
#define Nn 500
#define Hh 8

typedef unsigned long long ull;

__device__ float g_q[Bb * Hh * Nn * 16];
__device__ float g_k[Bb * Hh * Nn * 16];
__device__ float g_v[Bb * Hh * Nn * 16];
__device__ float g_att[Bb * Nn * 128];
__device__ float g_mh[Bb * Nn * 128];
__device__ unsigned g_maskbits[Bb * Nn * 16];

// ---- f32x2 helpers ---------------------------------------------------------
__device__ __forceinline__ ull fma2(ull a, ull b, ull c) {
    ull d;
    asm("fma.rn.f32x2 %0, %1, %2, %3;" : "=l"(d) : "l"(a), "l"(b), "l"(c));
    return d;
}
__device__ __forceinline__ ull pack2(float x, float y) {
    ull r;
    asm("mov.b64 %0, {%1, %2};" : "=l"(r) : "f"(x), "f"(y));
    return r;
}
__device__ __forceinline__ ull dup2(float x) {
    ull r;
    asm("mov.b64 %0, {%1, %1};" : "=l"(r) : "f"(x));
    return r;
}
__device__ __forceinline__ float2 unpack2(ull a) {
    float2 f;
    asm("mov.b64 {%0, %1}, %2;" : "=f"(f.x), "=f"(f.y) : "l"(a));
    return f;
}

// ---------------------------------------------------------------------------
// Projection body: out[m,f] = sum_e A[m,e] * W[f,e] (+ second pass) (+ bias)
// Tile 64 rows x 128 cols, K=128. 256 threads: warp ty -> rows ty*8..+7
// (broadcast LDS), lane tx -> cols f = tx + 32j (conflict-free LDS.128 from
// padded K-major Ws[f][132]). Packs over e-pairs: no transpose, no dup-MOVs.
// smem = 64*128 + 128*132 floats = 100352 B.
// ---------------------------------------------------------------------------
__device__ __forceinline__ void proj_body(const float* __restrict__ A0,
                                          const float* __restrict__ W0,
                                          const float* __restrict__ A1,
                                          const float* __restrict__ W1,
                                          const float* __restrict__ bias,
                                          float* __restrict__ out,
                                          int headsLayout, int m0) {
    extern __shared__ float sh[];
    float* Xs = sh;              // [64][128]
    float* Ws = sh + 64 * 128;   // [128][132] K-major, padded

    const int t = threadIdx.x;
    const int ty = t >> 5, tx = t & 31;

    ull acc[8][4];
    #pragma unroll
    for (int i = 0; i < 8; ++i)
        #pragma unroll
        for (int j = 0; j < 4; ++j) acc[i][j] = 0ULL;

    const int npass = (A1 != nullptr) ? 2 : 1;
    for (int pass = 0; pass < npass; ++pass) {
        const float* A = pass ? A1 : A0;
        const float* W = pass ? W1 : W0;
        if (pass) __syncthreads();
        const float4* A4 = (const float4*)(A + (size_t)m0 * 128);
        #pragma unroll
        for (int k = 0; k < 8; ++k)
            ((float4*)Xs)[t + 256 * k] = A4[t + 256 * k];
        const float4* W4 = (const float4*)W;
        #pragma unroll
        for (int k = 0; k < 16; ++k) {
            int i4 = t + 256 * k;
            int f = i4 >> 5, e4 = i4 & 31;
            *(float4*)(Ws + f * 132 + e4 * 4) = W4[i4];
        }
        __syncthreads();

        for (int e0 = 0; e0 < 128; e0 += 4) {
            ulonglong2 wv[4];
            #pragma unroll
            for (int j = 0; j < 4; ++j)
                wv[j] = *(const ulonglong2*)(Ws + (tx + 32 * j) * 132 + e0);
            #pragma unroll
            for (int i = 0; i < 8; ++i) {
                ulonglong2 xv =
                    *(const ulonglong2*)(Xs + (ty * 8 + i) * 128 + e0);
                #pragma unroll
                for (int j = 0; j < 4; ++j) {
                    acc[i][j] = fma2(xv.x, wv[j].x, acc[i][j]);
                    acc[i][j] = fma2(xv.y, wv[j].y, acc[i][j]);
                }
            }
        }
    }

    float bb[4] = {0.f, 0.f, 0.f, 0.f};
    if (bias) {
        #pragma unroll
        for (int j = 0; j < 4; ++j) bb[j] = bias[tx + 32 * j];
    }
    #pragma unroll
    for (int i = 0; i < 8; ++i) {
        int m = m0 + ty * 8 + i;
        int b = m / Nn, n = m - b * Nn;
        #pragma unroll
        for (int j = 0; j < 4; ++j) {
            int f = tx + 32 * j;
            float2 s = unpack2(acc[i][j]);
            float r = s.x + s.y + bb[j];
            if (headsLayout) {
                int h = f >> 4, d = f & 15;
                out[(((size_t)(b * Hh + h)) * Nn + n) * 16 + d] = r;
            } else {
                out[(size_t)m * 128 + f] = r;
            }
        }
    }
}

// ---------------------------------------------------------------------------
// Stage A: fused q/k/v projections + mask->bitmask
// ---------------------------------------------------------------------------
__global__ void __launch_bounds__(256, 2)
stageA_kernel(const float* __restrict__ enc_nodes,
              const float* __restrict__ enc_first,
              const float* __restrict__ enc_last,
              const float* __restrict__ mask,
              const float* __restrict__ Wqf, const float* __restrict__ Wql,
              const float* __restrict__ Wk, const float* __restrict__ Wv) {
    int bi = blockIdx.x;
    if (bi < 500) {
        proj_body(enc_first, Wqf, enc_last, Wql, nullptr, g_q, 1, bi * 64);
    } else if (bi < 1000) {
        proj_body(enc_nodes, Wk, nullptr, nullptr, nullptr, g_k, 1,
                  (bi - 500) * 64);
    } else if (bi < 1500) {
        proj_body(enc_nodes, Wv, nullptr, nullptr, nullptr, g_v, 1,
                  (bi - 1000) * 64);
    } else {
        // maskbits: 128 rows per block, warp per row group of 16
        int t = threadIdx.x;
        int wid = t >> 5, lane = t & 31;
        int rowbase = (bi - 1500) * 128 + wid * 16;
        for (int rr = 0; rr < 16; ++rr) {
            int row = rowbase + rr;
            const float* mrow = mask + (size_t)row * Nn;
            unsigned* brow = g_maskbits + (size_t)row * 16;
            #pragma unroll
            for (int w = 0; w < 16; ++w) {
                int g = w * 32 + lane;
                float v = (g < Nn) ? mrow[g] : -1e9f;
                unsigned bal = __ballot_sync(0xffffffffu, v > -1.0f);
                if (lane == 0) brow[w] = bal;
            }
        }
    }
}

// ---------------------------------------------------------------------------
// Attention: block = (b,h,half). 128 threads, 2 rows/thread, 250 rows/block.
// K,V in smem (64KB, zero-padded to 512 rows). Dots packed over d (f32x2).
// q pre-scaled by log2e/4 so p = exp2f(dot). Mask = multiplicative bit.
// ---------------------------------------------------------------------------
__global__ void __launch_bounds__(128, 3)
attn_kernel() {
    extern __shared__ float sh[];
    float* Ks = sh;               // [512][16]
    float* Vs = sh + 512 * 16;

    const int t = threadIdx.x;
    const int bi = blockIdx.x;
    const int bh = bi >> 1;
    const int half = bi & 1;
    const int b = bh >> 3;
    const int h = bh & 7;

    const float4* kp4 = (const float4*)(g_k + (size_t)bh * Nn * 16);
    const float4* vp4 = (const float4*)(g_v + (size_t)bh * Nn * 16);
    const float4 z4 = make_float4(0.f, 0.f, 0.f, 0.f);
    #pragma unroll
    for (int k = 0; k < 16; ++k) {
        int i4 = t + 128 * k;
        bool ok = i4 < Nn * 4;
        ((float4*)Ks)[i4] = ok ? kp4[i4] : z4;
        ((float4*)Vs)[i4] = ok ? vp4[i4] : z4;
    }
    __syncthreads();

    const int r0 = half * 250 + t;
    const bool has1 = (t < 122);
    const int r1 = r0 + 128;
    const int r1c = has1 ? r1 : r0;

    const float QS = 1.4426950408889634f * 0.25f;  // log2e / sqrt(D)
    ull q0p[8], q1p[8];
    {
        const float4* q0f = (const float4*)(g_q + ((size_t)bh * Nn + r0) * 16);
        const float4* q1f = (const float4*)(g_q + ((size_t)bh * Nn + r1c) * 16);
        #pragma unroll
        for (int j = 0; j < 4; ++j) {
            float4 a = q0f[j], c = q1f[j];
            q0p[2 * j]     = pack2(a.x * QS, a.y * QS);
            q0p[2 * j + 1] = pack2(a.z * QS, a.w * QS);
            q1p[2 * j]     = pack2(c.x * QS, c.y * QS);
            q1p[2 * j + 1] = pack2(c.z * QS, c.w * QS);
        }
    }
    const unsigned* mb0 = g_maskbits + ((size_t)b * Nn + r0) * 16;
    const unsigned* mb1 = g_maskbits + ((size_t)b * Nn + r1c) * 16;

    ull a0p[8], a1p[8];
    #pragma unroll
    for (int j = 0; j < 8; ++j) { a0p[j] = 0ULL; a1p[j] = 0ULL; }
    float l0 = 0.f, l1 = 0.f;

    for (int w16 = 0; w16 < 16; ++w16) {
        unsigned bits0 = mb0[w16];
        unsigned bits1 = has1 ? mb1[w16] : 0u;
        const ulonglong2* kg =
            (const ulonglong2*)(Ks + (size_t)w16 * 32 * 16);
        const ulonglong2* vg =
            (const ulonglong2*)(Vs + (size_t)w16 * 32 * 16);
        #pragma unroll 8
        for (int j = 0; j < 32; ++j) {
            ulonglong2 k0 = kg[j * 4 + 0], k1 = kg[j * 4 + 1];
            ulonglong2 k2 = kg[j * 4 + 2], k3 = kg[j * 4 + 3];
            ull s0 = fma2(q0p[0], k0.x, 0ULL);
            ull s1 = fma2(q1p[0], k0.x, 0ULL);
            s0 = fma2(q0p[1], k0.y, s0);  s1 = fma2(q1p[1], k0.y, s1);
            s0 = fma2(q0p[2], k1.x, s0);  s1 = fma2(q1p[2], k1.x, s1);
            s0 = fma2(q0p[3], k1.y, s0);  s1 = fma2(q1p[3], k1.y, s1);
            s0 = fma2(q0p[4], k2.x, s0);  s1 = fma2(q1p[4], k2.x, s1);
            s0 = fma2(q0p[5], k2.y, s0);  s1 = fma2(q1p[5], k2.y, s1);
            s0 = fma2(q0p[6], k3.x, s0);  s1 = fma2(q1p[6], k3.x, s1);
            s0 = fma2(q0p[7], k3.y, s0);  s1 = fma2(q1p[7], k3.y, s1);
            float2 u0 = unpack2(s0), u1 = unpack2(s1);
            float p0 = exp2f(u0.x + u0.y);
            float p1 = exp2f(u1.x + u1.y);
            p0 = ((bits0 >> j) & 1u) ? p0 : 0.f;
            p1 = ((bits1 >> j) & 1u) ? p1 : 0.f;
            l0 += p0; l1 += p1;
            ull pd0 = dup2(p0), pd1 = dup2(p1);
            ulonglong2 v0 = vg[j * 4 + 0], v1 = vg[j * 4 + 1];
            ulonglong2 v2 = vg[j * 4 + 2], v3 = vg[j * 4 + 3];
            a0p[0] = fma2(pd0, v0.x, a0p[0]); a1p[0] = fma2(pd1, v0.x, a1p[0]);
            a0p[1] = fma2(pd0, v0.y, a0p[1]); a1p[1] = fma2(pd1, v0.y, a1p[1]);
            a0p[2] = fma2(pd0, v1.x, a0p[2]); a1p[2] = fma2(pd1, v1.x, a1p[2]);
            a0p[3] = fma2(pd0, v1.y, a0p[3]); a1p[3] = fma2(pd1, v1.y, a1p[3]);
            a0p[4] = fma2(pd0, v2.x, a0p[4]); a1p[4] = fma2(pd1, v2.x, a1p[4]);
            a0p[5] = fma2(pd0, v2.y, a0p[5]); a1p[5] = fma2(pd1, v2.y, a1p[5]);
            a0p[6] = fma2(pd0, v3.x, a0p[6]); a1p[6] = fma2(pd1, v3.x, a1p[6]);
            a0p[7] = fma2(pd0, v3.y, a0p[7]); a1p[7] = fma2(pd1, v3.y, a1p[7]);
        }
    }

    {
        float inv0 = __fdividef(1.0f, l0);
        float4* o0 = (float4*)(g_att + ((size_t)b * Nn + r0) * 128 + h * 16);
        #pragma unroll
        for (int j = 0; j < 4; ++j) {
            float2 a = unpack2(a0p[2 * j]);
            float2 c = unpack2(a0p[2 * j + 1]);
            o0[j] = make_float4(a.x * inv0, a.y * inv0, c.x * inv0, c.y * inv0);
        }
    }
    if (has1) {
        float inv1 = __fdividef(1.0f, l1);
        float4* o1 = (float4*)(g_att + ((size_t)b * Nn + r1) * 128 + h * 16);
        #pragma unroll
        for (int j = 0; j < 4; ++j) {
            float2 a = unpack2(a1p[2 * j]);
            float2 c = unpack2(a1p[2 * j + 1]);
            o1[j] = make_float4(a.x * inv1, a.y * inv1, c.x * inv1, c.y * inv1);
        }
    }
}

// ---------------------------------------------------------------------------
// Combine: mh = att @ Wc^T + bc
// ---------------------------------------------------------------------------
__global__ void __launch_bounds__(256, 2)
combine_kernel(const float* __restrict__ Wc, const float* __restrict__ bc) {
    proj_body(g_att, Wc, nullptr, nullptr, bc, g_mh, 0, blockIdx.x * 64);
}

// ---------------------------------------------------------------------------
// Pointer attention + in-block softmax normalize.
// Block = (b, 64-row tile). 4 enc tiles of 128 g. Packed over e (no
// transpose). tanh via (u-1)/(u+1), u=exp(2x) (algebraically exact).
// Mask as bit-gate. Unnormalized p written to out, then in-block rescale.
// smem: Ms[64][128] + Es[128][132] + rsum[64] = 100608 B.
// ---------------------------------------------------------------------------
__global__ void __launch_bounds__(256, 2)
pointer_kernel(const float* __restrict__ enc, float* __restrict__ out) {
    extern __shared__ float sh[];
    float* Ms = sh;                     // [64][128]
    float* Es = sh + 64 * 128;          // [128][132]
    float* rsum = Es + 128 * 132;       // [64]

    const int t = threadIdx.x;
    const int ty = t >> 5, tx = t & 31;
    const int b = blockIdx.y;
    const int n0 = blockIdx.x * 64;

    // fill Ms (zero-pad rows >= N)
    const float4 z4 = make_float4(0.f, 0.f, 0.f, 0.f);
    #pragma unroll
    for (int k = 0; k < 8; ++k) {
        int i4 = t + 256 * k;
        int row = i4 >> 5;
        int n = n0 + row;
        ((float4*)Ms)[i4] =
            (n < Nn) ? ((const float4*)(g_mh + ((size_t)b * Nn + n) * 128))
                           [i4 & 31]
                     : z4;
    }

    const float C1 = 0.08838834764831845f * 2.0f * 1.4426950408889634f;
    const float C2 = 10.0f * 1.4426950408889634f;

    float rs[8];
    #pragma unroll
    for (int i = 0; i < 8; ++i) rs[i] = 0.f;

    for (int tile = 0; tile < 4; ++tile) {
        const int gbase = tile * 128;
        __syncthreads();
        // fill Es[g][e] K-major, pad 132 (coalesced LDG, conflict-free STS)
        #pragma unroll
        for (int k = 0; k < 16; ++k) {
            int i4 = t + 256 * k;
            int gl = i4 >> 5, e4 = i4 & 31;
            int g = gbase + gl;
            float4 val =
                (g < Nn)
                    ? ((const float4*)(enc + ((size_t)b * Nn + g) * 128))[e4]
                    : z4;
            *(float4*)(Es + gl * 132 + e4 * 4) = val;
        }
        __syncthreads();

        ull acc[8][4];
        #pragma unroll
        for (int i = 0; i < 8; ++i)
            #pragma unroll
            for (int j = 0; j < 4; ++j) acc[i][j] = 0ULL;

        for (int e0 = 0; e0 < 128; e0 += 4) {
            ulonglong2 wv[4];
            #pragma unroll
            for (int j = 0; j < 4; ++j)
                wv[j] = *(const ulonglong2*)(Es + (tx + 32 * j) * 132 + e0);
            #pragma unroll
            for (int i = 0; i < 8; ++i) {
                ulonglong2 xv =
                    *(const ulonglong2*)(Ms + (ty * 8 + i) * 128 + e0);
                #pragma unroll
                for (int j = 0; j < 4; ++j) {
                    acc[i][j] = fma2(xv.x, wv[j].x, acc[i][j]);
                    acc[i][j] = fma2(xv.y, wv[j].y, acc[i][j]);
                }
            }
        }

        // epilogue: tanh-clip, exp, bit-gate, write unnormalized
        #pragma unroll
        for (int i = 0; i < 8; ++i) {
            int n = n0 + ty * 8 + i;
            int nc = (n < Nn) ? n : (Nn - 1);
            uint4 wb = *(const uint4*)(g_maskbits + ((size_t)b * Nn + nc) * 16 +
                                       tile * 4);
            unsigned w[4] = {wb.x, wb.y, wb.z, wb.w};
            float* orow = out + ((size_t)b * Nn + n) * Nn;
            #pragma unroll
            for (int j = 0; j < 4; ++j) {
                int g = gbase + 32 * j + tx;
                float2 sv = unpack2(acc[i][j]);
                float dtot = sv.x + sv.y;
                float u = exp2f(dtot * C1);
                float th = 1.0f - __fdividef(2.0f, u + 1.0f);
                float p = exp2f(C2 * th);
                p = ((w[j] >> tx) & 1u) ? p : 0.f;
                rs[i] += p;
                if (n < Nn && g < Nn) orow[g] = p;
            }
        }
    }

    // rowsum reduce (each row owned by one warp)
    #pragma unroll
    for (int i = 0; i < 8; ++i) {
        float v = rs[i];
        v += __shfl_xor_sync(0xffffffffu, v, 16);
        v += __shfl_xor_sync(0xffffffffu, v, 8);
        v += __shfl_xor_sync(0xffffffffu, v, 4);
        v += __shfl_xor_sync(0xffffffffu, v, 2);
        v += __shfl_xor_sync(0xffffffffu, v, 1);
        if (tx == 0) rsum[ty * 8 + i] = v;
    }
    __syncthreads();

    // in-block rescale (L2-hot read-modify-write of own region)
    {
        int rr = t >> 2;         // 0..63
        int c0 = t & 3;
        int n = n0 + rr;
        if (n < Nn) {
            float inv = __fdividef(1.0f, rsum[rr]);
            float4* po = (float4*)(out + ((size_t)b * Nn + n) * Nn);
            #pragma unroll
            for (int c = 0; c < 32; ++c) {
                int cc = c0 + c * 4;
                if (cc < 125) {
                    float4 p = po[cc];
                    p.x *= inv; p.y *= inv; p.z *= inv; p.w *= inv;
                    po[cc] = p;
                }
            }
        }
    }
}

// ---------------------------------------------------------------------------
// Launch
// ---------------------------------------------------------------------------
extern "C" void kernel_launch(void* const* d_in, const int* in_sizes, int n_in,
                              void* d_out, int out_size) {
    const float* enc_nodes = (const float*)d_in[0];
    const float* enc_first = (const float*)d_in[1];
    const float* enc_last  = (const float*)d_in[2];
    const float* mask      = (const float*)d_in[3];
    const float* Wq_first  = (const float*)d_in[4];
    const float* Wq_last   = (const float*)d_in[5];
    const float* Wk        = (const float*)d_in[6];
    const float* Wv        = (const float*)d_in[7];
    const float* Wc        = (const float*)d_in[8];
    const float* bc        = (const float*)d_in[9];
    float* out = (float*)d_out;

    const int PROJ_SMEM = (64 * 128 + 128 * 132) * 4;        // 100352
    const int ATTN_SMEM = 2 * 512 * 16 * 4;                  // 65536
    const int PTR_SMEM  = (64 * 128 + 128 * 132 + 64) * 4;   // 100608

    static int configured = 0;
    if (!configured) {
        cudaFuncSetAttribute(stageA_kernel,
            cudaFuncAttributeMaxDynamicSharedMemorySize, PROJ_SMEM);
        cudaFuncSetAttribute(attn_kernel,
            cudaFuncAttributeMaxDynamicSharedMemorySize, ATTN_SMEM);
        cudaFuncSetAttribute(combine_kernel,
            cudaFuncAttributeMaxDynamicSharedMemorySize, PROJ_SMEM);
        cudaFuncSetAttribute(pointer_kernel,
            cudaFuncAttributeMaxDynamicSharedMemorySize, PTR_SMEM);
        configured = 1;
    }

    // A) fused q/k/v projections + maskbits (q blocks first: 2x work)
    stageA_kernel<<<1750, 256, PROJ_SMEM>>>(enc_nodes, enc_first, enc_last,
                                            mask, Wq_first, Wq_last, Wk, Wv);
    // B) attention
    attn_kernel<<<1024, 128, ATTN_SMEM>>>();
    // C) combine
    combine_kernel<<<500, 256, PROJ_SMEM>>>(Wc, bc);
    // D) pointer attention + softmax
    dim3 pgrid(8, Bb);
    pointer_kernel<<<pgrid, 256, PTR_SMEM>>>(enc_nodes, out);

    (void)in_sizes; (void)n_in; (void)out_size;
}

// round 4
// speedup vs baseline: 2.1446x; 1.0686x over previous
#include <cuda_runtime.h>
#include <cuda_bf16.h>
#include <math.h>

// ---------------------------------------------------------------------------
// POMO decoder v4 — fp32x2 pipeline + HMMA (mma.sync) split-bf16 pointer GEMM.
// (tcgen05 is unavailable: harness PTX targets sm_103 without the 'a' suffix.)
// B=64, N=500, E=128, H=8, D=16
// ---------------------------------------------------------------------------

#define Bb 64
#define Nn 500
#define Hh 8

typedef unsigned long long ull;

__device__ float g_q[Bb * Hh * Nn * 16];
__device__ float g_k[Bb * Hh * Nn * 16];
__device__ float g_v[Bb * Hh * Nn * 16];
__device__ float g_att[Bb * Nn * 128];
__device__ unsigned g_maskbits[Bb * Nn * 16];
// split bf16 buffers: [b][row(512 pad)][hi(128) | lo(128)]
__device__ __nv_bfloat16 g_mh_split[Bb * 512 * 256];
__device__ __nv_bfloat16 g_enc_split[Bb * 512 * 256];

// ---- f32x2 helpers ---------------------------------------------------------
__device__ __forceinline__ ull fma2(ull a, ull b, ull c) {
    ull d;
    asm("fma.rn.f32x2 %0, %1, %2, %3;" : "=l"(d) : "l"(a), "l"(b), "l"(c));
    return d;
}
__device__ __forceinline__ ull pack2(float x, float y) {
    ull r;
    asm("mov.b64 %0, {%1, %2};" : "=l"(r) : "f"(x), "f"(y));
    return r;
}
__device__ __forceinline__ ull dup2(float x) {
    ull r;
    asm("mov.b64 %0, {%1, %1};" : "=l"(r) : "f"(x));
    return r;
}
__device__ __forceinline__ float2 unpack2(ull a) {
    float2 f;
    asm("mov.b64 {%0, %1}, %2;" : "=f"(f.x), "=f"(f.y) : "l"(a));
    return f;
}

__device__ __forceinline__ unsigned smem_u32(const void* p) {
    unsigned a;
    asm("{ .reg .u64 t; cvta.to.shared.u64 t, %1; cvt.u32.u64 %0, t; }"
        : "=r"(a) : "l"(p));
    return a;
}

// ---- mma.sync / ldmatrix helpers (baseline sm_80+ PTX, fine on sm_103) -----
__device__ __forceinline__ void ldmx4(unsigned* r, unsigned addr) {
    asm volatile(
        "ldmatrix.sync.aligned.m8n8.x4.shared.b16 {%0,%1,%2,%3}, [%4];"
        : "=r"(r[0]), "=r"(r[1]), "=r"(r[2]), "=r"(r[3]) : "r"(addr));
}
__device__ __forceinline__ void mma16816(float* c, const unsigned* a,
                                         unsigned b0, unsigned b1) {
    asm volatile(
        "mma.sync.aligned.m16n8k16.row.col.f32.bf16.bf16.f32 "
        "{%0,%1,%2,%3}, {%4,%5,%6,%7}, {%8,%9}, {%0,%1,%2,%3};"
        : "+f"(c[0]), "+f"(c[1]), "+f"(c[2]), "+f"(c[3])
        : "r"(a[0]), "r"(a[1]), "r"(a[2]), "r"(a[3]), "r"(b0), "r"(b1));
}

// ---------------------------------------------------------------------------
// Projection body (f32x2). mode: 1 = heads fp32 layout, 2 = split bf16 -> mh.
// ---------------------------------------------------------------------------
__device__ __forceinline__ void proj_body(const float* __restrict__ A0,
                                          const float* __restrict__ W0,
                                          const float* __restrict__ A1,
                                          const float* __restrict__ W1,
                                          const float* __restrict__ bias,
                                          float* __restrict__ out,
                                          int mode, int m0) {
    extern __shared__ float sh[];
    float* Xs = sh;              // [64][128]
    float* Ws = sh + 64 * 128;   // [128][132] K-major, padded

    const int t = threadIdx.x;
    const int ty = t >> 5, tx = t & 31;

    ull acc[8][4];
    #pragma unroll
    for (int i = 0; i < 8; ++i)
        #pragma unroll
        for (int j = 0; j < 4; ++j) acc[i][j] = 0ULL;

    const int npass = (A1 != nullptr) ? 2 : 1;
    for (int pass = 0; pass < npass; ++pass) {
        const float* A = pass ? A1 : A0;
        const float* W = pass ? W1 : W0;
        if (pass) __syncthreads();
        const float4* A4 = (const float4*)(A + (size_t)m0 * 128);
        #pragma unroll
        for (int k = 0; k < 8; ++k)
            ((float4*)Xs)[t + 256 * k] = A4[t + 256 * k];
        const float4* W4 = (const float4*)W;
        #pragma unroll
        for (int k = 0; k < 16; ++k) {
            int i4 = t + 256 * k;
            int f = i4 >> 5, e4 = i4 & 31;
            *(float4*)(Ws + f * 132 + e4 * 4) = W4[i4];
        }
        __syncthreads();

        for (int e0 = 0; e0 < 128; e0 += 4) {
            ulonglong2 wv[4];
            #pragma unroll
            for (int j = 0; j < 4; ++j)
                wv[j] = *(const ulonglong2*)(Ws + (tx + 32 * j) * 132 + e0);
            #pragma unroll
            for (int i = 0; i < 8; ++i) {
                ulonglong2 xv =
                    *(const ulonglong2*)(Xs + (ty * 8 + i) * 128 + e0);
                #pragma unroll
                for (int j = 0; j < 4; ++j) {
                    acc[i][j] = fma2(xv.x, wv[j].x, acc[i][j]);
                    acc[i][j] = fma2(xv.y, wv[j].y, acc[i][j]);
                }
            }
        }
    }

    float bb[4] = {0.f, 0.f, 0.f, 0.f};
    if (bias) {
        #pragma unroll
        for (int j = 0; j < 4; ++j) bb[j] = bias[tx + 32 * j];
    }
    #pragma unroll
    for (int i = 0; i < 8; ++i) {
        int m = m0 + ty * 8 + i;
        int b = m / Nn, n = m - b * Nn;
        #pragma unroll
        for (int j = 0; j < 4; ++j) {
            int f = tx + 32 * j;
            float2 s = unpack2(acc[i][j]);
            float r = s.x + s.y + bb[j];
            if (mode == 1) {
                int h = f >> 4, d = f & 15;
                out[(((size_t)(b * Hh + h)) * Nn + n) * 16 + d] = r;
            } else {
                __nv_bfloat16 hi = __float2bfloat16(r);
                float lo = r - __bfloat162float(hi);
                size_t base = ((size_t)(b * 512 + n)) * 256;
                g_mh_split[base + f] = hi;
                g_mh_split[base + 128 + f] = __float2bfloat16(lo);
            }
        }
    }
}

// ---------------------------------------------------------------------------
// Stage A: fused q/k/v projections + maskbits + enc split
// ---------------------------------------------------------------------------
__global__ void __launch_bounds__(256, 2)
stageA_kernel(const float* __restrict__ enc_nodes,
              const float* __restrict__ enc_first,
              const float* __restrict__ enc_last,
              const float* __restrict__ mask,
              const float* __restrict__ Wqf, const float* __restrict__ Wql,
              const float* __restrict__ Wk, const float* __restrict__ Wv) {
    int bi = blockIdx.x;
    if (bi < 500) {
        proj_body(enc_first, Wqf, enc_last, Wql, nullptr, g_q, 1, bi * 64);
    } else if (bi < 1000) {
        proj_body(enc_nodes, Wk, nullptr, nullptr, nullptr, g_k, 1,
                  (bi - 500) * 64);
    } else if (bi < 1500) {
        proj_body(enc_nodes, Wv, nullptr, nullptr, nullptr, g_v, 1,
                  (bi - 1000) * 64);
    } else if (bi < 1750) {
        // maskbits: 128 rows per block
        int t = threadIdx.x;
        int wid = t >> 5, lane = t & 31;
        int rowbase = (bi - 1500) * 128 + wid * 16;
        for (int rr = 0; rr < 16; ++rr) {
            int row = rowbase + rr;
            const float* mrow = mask + (size_t)row * Nn;
            unsigned* brow = g_maskbits + (size_t)row * 16;
            #pragma unroll
            for (int w = 0; w < 16; ++w) {
                int g = w * 32 + lane;
                float v = (g < Nn) ? mrow[g] : -1e9f;
                unsigned bal = __ballot_sync(0xffffffffu, v > -1.0f);
                if (lane == 0) brow[w] = bal;
            }
        }
    } else {
        // enc split: one batch per block (64 blocks)
        int b = bi - 1750;
        int t = threadIdx.x;
        const float4* src = (const float4*)(enc_nodes + (size_t)b * Nn * 128);
        for (int i4 = t; i4 < Nn * 32; i4 += 256) {
            int n = i4 >> 5, e4 = i4 & 31;
            float4 v = src[i4];
            __nv_bfloat162 h01 = __floats2bfloat162_rn(v.x, v.y);
            __nv_bfloat162 h23 = __floats2bfloat162_rn(v.z, v.w);
            float2 hf01 = __bfloat1622float2(h01);
            float2 hf23 = __bfloat1622float2(h23);
            __nv_bfloat162 l01 =
                __floats2bfloat162_rn(v.x - hf01.x, v.y - hf01.y);
            __nv_bfloat162 l23 =
                __floats2bfloat162_rn(v.z - hf23.x, v.w - hf23.y);
            __nv_bfloat16* dst =
                g_enc_split + ((size_t)(b * 512 + n)) * 256 + e4 * 4;
            *(__nv_bfloat162*)(dst) = h01;
            *(__nv_bfloat162*)(dst + 2) = h23;
            *(__nv_bfloat162*)(dst + 128) = l01;
            *(__nv_bfloat162*)(dst + 130) = l23;
        }
    }
}

// ---------------------------------------------------------------------------
// Attention (f32x2, unchanged)
// ---------------------------------------------------------------------------
__global__ void __launch_bounds__(128, 3)
attn_kernel() {
    extern __shared__ float sh[];
    float* Ks = sh;
    float* Vs = sh + 512 * 16;

    const int t = threadIdx.x;
    const int bi = blockIdx.x;
    const int bh = bi >> 1;
    const int half = bi & 1;
    const int b = bh >> 3;
    const int h = bh & 7;

    const float4* kp4 = (const float4*)(g_k + (size_t)bh * Nn * 16);
    const float4* vp4 = (const float4*)(g_v + (size_t)bh * Nn * 16);
    const float4 z4 = make_float4(0.f, 0.f, 0.f, 0.f);
    #pragma unroll
    for (int k = 0; k < 16; ++k) {
        int i4 = t + 128 * k;
        bool ok = i4 < Nn * 4;
        ((float4*)Ks)[i4] = ok ? kp4[i4] : z4;
        ((float4*)Vs)[i4] = ok ? vp4[i4] : z4;
    }
    __syncthreads();

    const int r0 = half * 250 + t;
    const bool has1 = (t < 122);
    const int r1 = r0 + 128;
    const int r1c = has1 ? r1 : r0;

    const float QS = 1.4426950408889634f * 0.25f;
    ull q0p[8], q1p[8];
    {
        const float4* q0f = (const float4*)(g_q + ((size_t)bh * Nn + r0) * 16);
        const float4* q1f = (const float4*)(g_q + ((size_t)bh * Nn + r1c) * 16);
        #pragma unroll
        for (int j = 0; j < 4; ++j) {
            float4 a = q0f[j], c = q1f[j];
            q0p[2 * j]     = pack2(a.x * QS, a.y * QS);
            q0p[2 * j + 1] = pack2(a.z * QS, a.w * QS);
            q1p[2 * j]     = pack2(c.x * QS, c.y * QS);
            q1p[2 * j + 1] = pack2(c.z * QS, c.w * QS);
        }
    }
    const unsigned* mb0 = g_maskbits + ((size_t)b * Nn + r0) * 16;
    const unsigned* mb1 = g_maskbits + ((size_t)b * Nn + r1c) * 16;

    ull a0p[8], a1p[8];
    #pragma unroll
    for (int j = 0; j < 8; ++j) { a0p[j] = 0ULL; a1p[j] = 0ULL; }
    float l0 = 0.f, l1 = 0.f;

    for (int w16 = 0; w16 < 16; ++w16) {
        unsigned bits0 = mb0[w16];
        unsigned bits1 = has1 ? mb1[w16] : 0u;
        const ulonglong2* kg = (const ulonglong2*)(Ks + (size_t)w16 * 32 * 16);
        const ulonglong2* vg = (const ulonglong2*)(Vs + (size_t)w16 * 32 * 16);
        #pragma unroll 8
        for (int j = 0; j < 32; ++j) {
            ulonglong2 k0 = kg[j * 4 + 0], k1 = kg[j * 4 + 1];
            ulonglong2 k2 = kg[j * 4 + 2], k3 = kg[j * 4 + 3];
            ull s0 = fma2(q0p[0], k0.x, 0ULL);
            ull s1 = fma2(q1p[0], k0.x, 0ULL);
            s0 = fma2(q0p[1], k0.y, s0);  s1 = fma2(q1p[1], k0.y, s1);
            s0 = fma2(q0p[2], k1.x, s0);  s1 = fma2(q1p[2], k1.x, s1);
            s0 = fma2(q0p[3], k1.y, s0);  s1 = fma2(q1p[3], k1.y, s1);
            s0 = fma2(q0p[4], k2.x, s0);  s1 = fma2(q1p[4], k2.x, s1);
            s0 = fma2(q0p[5], k2.y, s0);  s1 = fma2(q1p[5], k2.y, s1);
            s0 = fma2(q0p[6], k3.x, s0);  s1 = fma2(q1p[6], k3.x, s1);
            s0 = fma2(q0p[7], k3.y, s0);  s1 = fma2(q1p[7], k3.y, s1);
            float2 u0 = unpack2(s0), u1 = unpack2(s1);
            float p0 = exp2f(u0.x + u0.y);
            float p1 = exp2f(u1.x + u1.y);
            p0 = ((bits0 >> j) & 1u) ? p0 : 0.f;
            p1 = ((bits1 >> j) & 1u) ? p1 : 0.f;
            l0 += p0; l1 += p1;
            ull pd0 = dup2(p0), pd1 = dup2(p1);
            ulonglong2 v0 = vg[j * 4 + 0], v1 = vg[j * 4 + 1];
            ulonglong2 v2 = vg[j * 4 + 2], v3 = vg[j * 4 + 3];
            a0p[0] = fma2(pd0, v0.x, a0p[0]); a1p[0] = fma2(pd1, v0.x, a1p[0]);
            a0p[1] = fma2(pd0, v0.y, a0p[1]); a1p[1] = fma2(pd1, v0.y, a1p[1]);
            a0p[2] = fma2(pd0, v1.x, a0p[2]); a1p[2] = fma2(pd1, v1.x, a1p[2]);
            a0p[3] = fma2(pd0, v1.y, a0p[3]); a1p[3] = fma2(pd1, v1.y, a1p[3]);
            a0p[4] = fma2(pd0, v2.x, a0p[4]); a1p[4] = fma2(pd1, v2.x, a1p[4]);
            a0p[5] = fma2(pd0, v2.y, a0p[5]); a1p[5] = fma2(pd1, v2.y, a1p[5]);
            a0p[6] = fma2(pd0, v3.x, a0p[6]); a1p[6] = fma2(pd1, v3.x, a1p[6]);
            a0p[7] = fma2(pd0, v3.y, a0p[7]); a1p[7] = fma2(pd1, v3.y, a1p[7]);
        }
    }

    {
        float inv0 = __fdividef(1.0f, l0);
        float4* o0 = (float4*)(g_att + ((size_t)b * Nn + r0) * 128 + h * 16);
        #pragma unroll
        for (int j = 0; j < 4; ++j) {
            float2 a = unpack2(a0p[2 * j]);
            float2 c = unpack2(a0p[2 * j + 1]);
            o0[j] = make_float4(a.x * inv0, a.y * inv0, c.x * inv0, c.y * inv0);
        }
    }
    if (has1) {
        float inv1 = __fdividef(1.0f, l1);
        float4* o1 = (float4*)(g_att + ((size_t)b * Nn + r1) * 128 + h * 16);
        #pragma unroll
        for (int j = 0; j < 4; ++j) {
            float2 a = unpack2(a1p[2 * j]);
            float2 c = unpack2(a1p[2 * j + 1]);
            o1[j] = make_float4(a.x * inv1, a.y * inv1, c.x * inv1, c.y * inv1);
        }
    }
}

// ---------------------------------------------------------------------------
// Combine: mh = att @ Wc^T + bc -> split bf16 directly
// ---------------------------------------------------------------------------
__global__ void __launch_bounds__(256, 2)
combine_kernel(const float* __restrict__ Wc, const float* __restrict__ bc) {
    proj_body(g_att, Wc, nullptr, nullptr, bc, nullptr, 2, blockIdx.x * 64);
}

// ---------------------------------------------------------------------------
// Pointer stage via mma.sync (HMMA), split-bf16 3-pass error correction:
//   S = Ahi.Bhi + Ahi.Blo + Alo.Bhi   (residual ~2^-17)
// Block = (b, 128-row tile). 8 warps; warp w owns m16 stripe rows w*16..+15.
// A tile [128][264] bf16 (hi|lo, pad), cached as register fragments across
// all 4 g-tiles. B tile [128][264] per g-tile. Epilogue: tanh-clip + exp +
// bit-gate, quad rowsums, unnormalized STG, then in-block RMW rescale.
// smem: As 67584 + Bs 67584 + rsum 512 = 135680 B.
// ---------------------------------------------------------------------------
#define AS_STRIDE 264
#define PTR_SMEM (128 * AS_STRIDE * 2 * 2 + 512)

__global__ void __launch_bounds__(256, 1)
pointer_mma_kernel(float* __restrict__ out) {
    extern __shared__ char smem[];
    __nv_bfloat16* As = (__nv_bfloat16*)smem;
    __nv_bfloat16* Bs = As + 128 * AS_STRIDE;
    float* rsum = (float*)(Bs + 128 * AS_STRIDE);

    const int t = threadIdx.x;
    const int w = t >> 5, lane = t & 31;
    const int b = blockIdx.x >> 2;
    const int nt4 = blockIdx.x & 3;
    const int n0 = nt4 * 128;

    // fill A tile (rows n0..n0+127 of mh_split; rows >=500 read zeros)
    {
        const uint4* src =
            (const uint4*)(g_mh_split + ((size_t)(b * 512 + n0)) * 256);
        #pragma unroll
        for (int k = 0; k < 16; ++k) {
            int i4 = t + 256 * k;
            int row = i4 >> 5, c8 = i4 & 31;
            *(uint4*)(As + row * AS_STRIDE + c8 * 8) = src[i4];
        }
    }
    __syncthreads();

    // cache A fragments: af_hi/af_lo[kk][4]
    unsigned af_hi[8][4], af_lo[8][4];
    {
        unsigned rowa = w * 16 + (lane & 15);
        unsigned colbase = (lane >> 4) * 8;
        #pragma unroll
        for (int kk = 0; kk < 8; ++kk) {
            unsigned addr = smem_u32(As + rowa * AS_STRIDE + colbase + kk * 16);
            ldmx4(af_hi[kk], addr);
            ldmx4(af_lo[kk], addr + 128 * 2);
        }
    }

    const float C1 = 0.08838834764831845f * 2.0f * 1.4426950408889634f;
    const float C2 = 10.0f * 1.4426950408889634f;

    const int nr0 = n0 + w * 16 + (lane >> 2);
    const int nr1 = nr0 + 8;
    const int nr0c = (nr0 < Nn) ? nr0 : 0;
    const int nr1c = (nr1 < Nn) ? nr1 : 0;
    float rs0 = 0.f, rs1 = 0.f;

    for (int gt = 0; gt < 4; ++gt) {
        const int g0 = gt * 128;
        __syncthreads();
        {
            const uint4* src =
                (const uint4*)(g_enc_split + ((size_t)(b * 512 + g0)) * 256);
            #pragma unroll
            for (int k = 0; k < 16; ++k) {
                int i4 = t + 256 * k;
                int row = i4 >> 5, c8 = i4 & 31;
                *(uint4*)(Bs + row * AS_STRIDE + c8 * 8) = src[i4];
            }
        }
        __syncthreads();

        float acc[16][4];
        #pragma unroll
        for (int i = 0; i < 16; ++i)
            acc[i][0] = acc[i][1] = acc[i][2] = acc[i][3] = 0.f;

        unsigned browb = (lane & 15);
        unsigned bcolb = (lane >> 4) * 8;
        #pragma unroll
        for (int kk = 0; kk < 8; ++kk) {
            #pragma unroll
            for (int np = 0; np < 8; ++np) {
                unsigned baddr = smem_u32(Bs + (np * 16 + browb) * AS_STRIDE +
                                          bcolb + kk * 16);
                unsigned bh[4], bl[4];
                ldmx4(bh, baddr);
                ldmx4(bl, baddr + 128 * 2);
                // pass0: Ahi*Bhi ; pass1: Ahi*Blo ; pass2: Alo*Bhi
                mma16816(acc[2 * np],     af_hi[kk], bh[0], bh[2]);
                mma16816(acc[2 * np + 1], af_hi[kk], bh[1], bh[3]);
                mma16816(acc[2 * np],     af_hi[kk], bl[0], bl[2]);
                mma16816(acc[2 * np + 1], af_hi[kk], bl[1], bl[3]);
                mma16816(acc[2 * np],     af_lo[kk], bh[0], bh[2]);
                mma16816(acc[2 * np + 1], af_lo[kk], bh[1], bh[3]);
            }
        }

        // epilogue for this g-tile
        uint4 m0 = *(const uint4*)(g_maskbits + ((size_t)b * Nn + nr0c) * 16 +
                                   gt * 4);
        uint4 m1 = *(const uint4*)(g_maskbits + ((size_t)b * Nn + nr1c) * 16 +
                                   gt * 4);
        unsigned mw0[4] = {m0.x, m0.y, m0.z, m0.w};
        unsigned mw1[4] = {m1.x, m1.y, m1.z, m1.w};

        #pragma unroll
        for (int ntile = 0; ntile < 16; ++ntile) {
            unsigned w0 = mw0[ntile >> 2];
            unsigned w1 = mw1[ntile >> 2];
            int bitb = (ntile & 3) * 8 + (lane & 3) * 2;
            float p00, p01, p10, p11;
            {
                float u = exp2f(acc[ntile][0] * C1);
                float th = 1.0f - __fdividef(2.0f, u + 1.0f);
                p00 = exp2f(C2 * th);
            }
            {
                float u = exp2f(acc[ntile][1] * C1);
                float th = 1.0f - __fdividef(2.0f, u + 1.0f);
                p01 = exp2f(C2 * th);
            }
            {
                float u = exp2f(acc[ntile][2] * C1);
                float th = 1.0f - __fdividef(2.0f, u + 1.0f);
                p10 = exp2f(C2 * th);
            }
            {
                float u = exp2f(acc[ntile][3] * C1);
                float th = 1.0f - __fdividef(2.0f, u + 1.0f);
                p11 = exp2f(C2 * th);
            }
            p00 = ((w0 >> bitb) & 1u) ? p00 : 0.f;
            p01 = ((w0 >> (bitb + 1)) & 1u) ? p01 : 0.f;
            p10 = ((w1 >> bitb) & 1u) ? p10 : 0.f;
            p11 = ((w1 >> (bitb + 1)) & 1u) ? p11 : 0.f;
            rs0 += p00 + p01;
            rs1 += p10 + p11;
            int g = g0 + ntile * 8 + (lane & 3) * 2;
            if (g < Nn) {
                if (nr0 < Nn)
                    *(float2*)(out + ((size_t)b * Nn + nr0) * Nn + g) =
                        make_float2(p00, p01);
                if (nr1 < Nn)
                    *(float2*)(out + ((size_t)b * Nn + nr1) * Nn + g) =
                        make_float2(p10, p11);
            }
        }
    }

    // quad-reduce row sums (lanes sharing lane>>2 own same row)
    rs0 += __shfl_xor_sync(0xffffffffu, rs0, 1);
    rs0 += __shfl_xor_sync(0xffffffffu, rs0, 2);
    rs1 += __shfl_xor_sync(0xffffffffu, rs1, 1);
    rs1 += __shfl_xor_sync(0xffffffffu, rs1, 2);
    if ((lane & 3) == 0) {
        rsum[w * 16 + (lane >> 2)] = rs0;
        rsum[w * 16 + (lane >> 2) + 8] = rs1;
    }
    __syncthreads();

    // rescale: 128 rows x 125 float4
    for (int i4 = t; i4 < 128 * 125; i4 += 256) {
        int row = i4 / 125, c4 = i4 - row * 125;
        int n = n0 + row;
        if (n < Nn) {
            float inv = __fdividef(1.0f, rsum[row]);
            float4* po = (float4*)(out + ((size_t)b * Nn + n) * Nn) + c4;
            float4 p = *po;
            p.x *= inv; p.y *= inv; p.z *= inv; p.w *= inv;
            *po = p;
        }
    }
}

// ---------------------------------------------------------------------------
// Launch
// ---------------------------------------------------------------------------
extern "C" void kernel_launch(void* const* d_in, const int* in_sizes, int n_in,
                              void* d_out, int out_size) {
    const float* enc_nodes = (const float*)d_in[0];
    const float* enc_first = (const float*)d_in[1];
    const float* enc_last  = (const float*)d_in[2];
    const float* mask      = (const float*)d_in[3];
    const float* Wq_first  = (const float*)d_in[4];
    const float* Wq_last   = (const float*)d_in[5];
    const float* Wk        = (const float*)d_in[6];
    const float* Wv        = (const float*)d_in[7];
    const float* Wc        = (const float*)d_in[8];
    const float* bc        = (const float*)d_in[9];
    float* out = (float*)d_out;

    const int PROJ_SMEM = (64 * 128 + 128 * 132) * 4;   // 100352
    const int ATTN_SMEM = 2 * 512 * 16 * 4;             // 65536

    static int configured = 0;
    if (!configured) {
        cudaFuncSetAttribute(stageA_kernel,
            cudaFuncAttributeMaxDynamicSharedMemorySize, PROJ_SMEM);
        cudaFuncSetAttribute(attn_kernel,
            cudaFuncAttributeMaxDynamicSharedMemorySize, ATTN_SMEM);
        cudaFuncSetAttribute(combine_kernel,
            cudaFuncAttributeMaxDynamicSharedMemorySize, PROJ_SMEM);
        cudaFuncSetAttribute(pointer_mma_kernel,
            cudaFuncAttributeMaxDynamicSharedMemorySize, PTR_SMEM);
        configured = 1;
    }

    // A) q/k/v projections + maskbits + enc split
    stageA_kernel<<<1814, 256, PROJ_SMEM>>>(enc_nodes, enc_first, enc_last,
                                            mask, Wq_first, Wq_last, Wk, Wv);
    // B) attention
    attn_kernel<<<1024, 128, ATTN_SMEM>>>();
    // C) combine -> mh split bf16
    combine_kernel<<<500, 256, PROJ_SMEM>>>(Wc, bc);
    // D) pointer attention via HMMA
    pointer_mma_kernel<<<Bb * 4, 256, PTR_SMEM>>>(out);

    (void)in_sizes; (void)n_in; (void)out_size;
}

// round 5
// speedup vs baseline: 2.6775x; 1.2485x over previous
#include <cuda_runtime.h>
#include <cuda_bf16.h>
#include <math.h>

// ---------------------------------------------------------------------------
// POMO decoder v5 — HMMA split-bf16 attention + pointer; f32x2 projections.
// B=64, N=500, E=128, H=8, D=16
// ---------------------------------------------------------------------------

#define Bb 64
#define Nn 500
#define Hh 8
#define QKV_STRIDE 40   // [hi 16 | lo 16 | pad 8] bf16 => 80B rows (LDSM clean)

typedef unsigned long long ull;

__device__ float g_att[Bb * Nn * 128];
__device__ unsigned g_maskbits[Bb * Nn * 16];
// split bf16: q/k/v per (b,h): [512 rows][40], q pre-scaled by log2e/4
__device__ __nv_bfloat16 g_q_split[Bb * Hh * 512 * QKV_STRIDE];
__device__ __nv_bfloat16 g_k_split[Bb * Hh * 512 * QKV_STRIDE];
__device__ __nv_bfloat16 g_v_split[Bb * Hh * 512 * QKV_STRIDE];
// split bf16: [b][row 512][hi 128 | lo 128]
__device__ __nv_bfloat16 g_mh_split[Bb * 512 * 256];
__device__ __nv_bfloat16 g_enc_split[Bb * 512 * 256];

// ---- f32x2 helpers ---------------------------------------------------------
__device__ __forceinline__ ull fma2(ull a, ull b, ull c) {
    ull d;
    asm("fma.rn.f32x2 %0, %1, %2, %3;" : "=l"(d) : "l"(a), "l"(b), "l"(c));
    return d;
}
__device__ __forceinline__ float2 unpack2(ull a) {
    float2 f;
    asm("mov.b64 {%0, %1}, %2;" : "=f"(f.x), "=f"(f.y) : "l"(a));
    return f;
}

__device__ __forceinline__ unsigned smem_u32(const void* p) {
    unsigned a;
    asm("{ .reg .u64 t; cvta.to.shared.u64 t, %1; cvt.u32.u64 %0, t; }"
        : "=r"(a) : "l"(p));
    return a;
}

// ---- mma.sync / ldmatrix helpers -------------------------------------------
__device__ __forceinline__ void ldmx4(unsigned* r, unsigned addr) {
    asm volatile(
        "ldmatrix.sync.aligned.m8n8.x4.shared.b16 {%0,%1,%2,%3}, [%4];"
        : "=r"(r[0]), "=r"(r[1]), "=r"(r[2]), "=r"(r[3]) : "r"(addr));
}
__device__ __forceinline__ void ldmx4t(unsigned* r, unsigned addr) {
    asm volatile(
        "ldmatrix.sync.aligned.m8n8.x4.trans.shared.b16 {%0,%1,%2,%3}, [%4];"
        : "=r"(r[0]), "=r"(r[1]), "=r"(r[2]), "=r"(r[3]) : "r"(addr));
}
__device__ __forceinline__ void mma16816(float* c, const unsigned* a,
                                         unsigned b0, unsigned b1) {
    asm volatile(
        "mma.sync.aligned.m16n8k16.row.col.f32.bf16.bf16.f32 "
        "{%0,%1,%2,%3}, {%4,%5,%6,%7}, {%8,%9}, {%0,%1,%2,%3};"
        : "+f"(c[0]), "+f"(c[1]), "+f"(c[2]), "+f"(c[3])
        : "r"(a[0]), "r"(a[1]), "r"(a[2]), "r"(a[3]), "r"(b0), "r"(b1));
}
__device__ __forceinline__ unsigned pack_bf2(float x, float y) {
    __nv_bfloat162 h = __floats2bfloat162_rn(x, y);
    return *(unsigned*)&h;
}

// ---------------------------------------------------------------------------
// Projection body (f32x2). mode 1: split-bf16 heads layout (q/k/v, scale).
// mode 2: split-bf16 mh layout.
// ---------------------------------------------------------------------------
__device__ __forceinline__ void proj_body(const float* __restrict__ A0,
                                          const float* __restrict__ W0,
                                          const float* __restrict__ A1,
                                          const float* __restrict__ W1,
                                          const float* __restrict__ bias,
                                          __nv_bfloat16* __restrict__ outb,
                                          float oscale, int mode, int m0) {
    extern __shared__ float sh[];
    float* Xs = sh;              // [64][128]
    float* Ws = sh + 64 * 128;   // [128][132] K-major, padded

    const int t = threadIdx.x;
    const int ty = t >> 5, tx = t & 31;

    ull acc[8][4];
    #pragma unroll
    for (int i = 0; i < 8; ++i)
        #pragma unroll
        for (int j = 0; j < 4; ++j) acc[i][j] = 0ULL;

    const int npass = (A1 != nullptr) ? 2 : 1;
    for (int pass = 0; pass < npass; ++pass) {
        const float* A = pass ? A1 : A0;
        const float* W = pass ? W1 : W0;
        if (pass) __syncthreads();
        const float4* A4 = (const float4*)(A + (size_t)m0 * 128);
        #pragma unroll
        for (int k = 0; k < 8; ++k)
            ((float4*)Xs)[t + 256 * k] = A4[t + 256 * k];
        const float4* W4 = (const float4*)W;
        #pragma unroll
        for (int k = 0; k < 16; ++k) {
            int i4 = t + 256 * k;
            int f = i4 >> 5, e4 = i4 & 31;
            *(float4*)(Ws + f * 132 + e4 * 4) = W4[i4];
        }
        __syncthreads();

        for (int e0 = 0; e0 < 128; e0 += 4) {
            ulonglong2 wv[4];
            #pragma unroll
            for (int j = 0; j < 4; ++j)
                wv[j] = *(const ulonglong2*)(Ws + (tx + 32 * j) * 132 + e0);
            #pragma unroll
            for (int i = 0; i < 8; ++i) {
                ulonglong2 xv =
                    *(const ulonglong2*)(Xs + (ty * 8 + i) * 128 + e0);
                #pragma unroll
                for (int j = 0; j < 4; ++j) {
                    acc[i][j] = fma2(xv.x, wv[j].x, acc[i][j]);
                    acc[i][j] = fma2(xv.y, wv[j].y, acc[i][j]);
                }
            }
        }
    }

    float bb[4] = {0.f, 0.f, 0.f, 0.f};
    if (bias) {
        #pragma unroll
        for (int j = 0; j < 4; ++j) bb[j] = bias[tx + 32 * j];
    }
    #pragma unroll
    for (int i = 0; i < 8; ++i) {
        int m = m0 + ty * 8 + i;
        int b = m / Nn, n = m - b * Nn;
        #pragma unroll
        for (int j = 0; j < 4; ++j) {
            int f = tx + 32 * j;
            float2 s = unpack2(acc[i][j]);
            float r = (s.x + s.y + bb[j]) * oscale;
            __nv_bfloat16 hi = __float2bfloat16(r);
            float lo = r - __bfloat162float(hi);
            if (mode == 1) {
                int h = f >> 4, d = f & 15;
                size_t base =
                    ((size_t)((b * Hh + h) * 512 + n)) * QKV_STRIDE + d;
                outb[base] = hi;
                outb[base + 16] = __float2bfloat16(lo);
            } else {
                size_t base = ((size_t)(b * 512 + n)) * 256;
                g_mh_split[base + f] = hi;
                g_mh_split[base + 128 + f] = __float2bfloat16(lo);
            }
        }
    }
}

// ---------------------------------------------------------------------------
// Stage A: fused q/k/v projections + maskbits + enc split
// ---------------------------------------------------------------------------
__global__ void __launch_bounds__(256, 2)
stageA_kernel(const float* __restrict__ enc_nodes,
              const float* __restrict__ enc_first,
              const float* __restrict__ enc_last,
              const float* __restrict__ mask,
              const float* __restrict__ Wqf, const float* __restrict__ Wql,
              const float* __restrict__ Wk, const float* __restrict__ Wv) {
    const float QS = 1.4426950408889634f * 0.25f;  // log2e / sqrt(D)
    int bi = blockIdx.x;
    if (bi < 500) {
        proj_body(enc_first, Wqf, enc_last, Wql, nullptr, g_q_split, QS, 1,
                  bi * 64);
    } else if (bi < 1000) {
        proj_body(enc_nodes, Wk, nullptr, nullptr, nullptr, g_k_split, 1.0f, 1,
                  (bi - 500) * 64);
    } else if (bi < 1500) {
        proj_body(enc_nodes, Wv, nullptr, nullptr, nullptr, g_v_split, 1.0f, 1,
                  (bi - 1000) * 64);
    } else if (bi < 1750) {
        // maskbits: 128 rows per block
        int t = threadIdx.x;
        int wid = t >> 5, lane = t & 31;
        int rowbase = (bi - 1500) * 128 + wid * 16;
        for (int rr = 0; rr < 16; ++rr) {
            int row = rowbase + rr;
            const float* mrow = mask + (size_t)row * Nn;
            unsigned* brow = g_maskbits + (size_t)row * 16;
            #pragma unroll
            for (int w = 0; w < 16; ++w) {
                int g = w * 32 + lane;
                float v = (g < Nn) ? mrow[g] : -1e9f;
                unsigned bal = __ballot_sync(0xffffffffu, v > -1.0f);
                if (lane == 0) brow[w] = bal;
            }
        }
    } else {
        // enc split: one batch per block (64 blocks)
        int b = bi - 1750;
        int t = threadIdx.x;
        const float4* src = (const float4*)(enc_nodes + (size_t)b * Nn * 128);
        for (int i4 = t; i4 < Nn * 32; i4 += 256) {
            int n = i4 >> 5, e4 = i4 & 31;
            float4 v = src[i4];
            __nv_bfloat162 h01 = __floats2bfloat162_rn(v.x, v.y);
            __nv_bfloat162 h23 = __floats2bfloat162_rn(v.z, v.w);
            float2 hf01 = __bfloat1622float2(h01);
            float2 hf23 = __bfloat1622float2(h23);
            __nv_bfloat162 l01 =
                __floats2bfloat162_rn(v.x - hf01.x, v.y - hf01.y);
            __nv_bfloat162 l23 =
                __floats2bfloat162_rn(v.z - hf23.x, v.w - hf23.y);
            __nv_bfloat16* dst =
                g_enc_split + ((size_t)(b * 512 + n)) * 256 + e4 * 4;
            *(__nv_bfloat162*)(dst) = h01;
            *(__nv_bfloat162*)(dst + 2) = h23;
            *(__nv_bfloat162*)(dst + 128) = l01;
            *(__nv_bfloat162*)(dst + 130) = l23;
        }
    }
}

// ---------------------------------------------------------------------------
// Attention via HMMA, split-bf16 3-pass for both GEMMs.
// Block = (b,h,qtile): 128 q-rows, 8 warps, warp -> m16 stripe.
// S = q.k (q pre-scaled): p = exp2(S) * bit; P split hi/lo in-register
// (C-frag -> A-frag identity), AV accumulated 3-pass. No-max softmax.
// smem: Qs 128x40 + Ks 512x40 + Vs 512x40 bf16 = 92160 B.
// ---------------------------------------------------------------------------
#define ATT_SMEM ((128 + 512 + 512) * QKV_STRIDE * 2)

__global__ void __launch_bounds__(256, 2)
attn_mma_kernel() {
    extern __shared__ char smem[];
    __nv_bfloat16* Qs = (__nv_bfloat16*)smem;
    __nv_bfloat16* Ks = Qs + 128 * QKV_STRIDE;
    __nv_bfloat16* Vs = Ks + 512 * QKV_STRIDE;

    const int t = threadIdx.x;
    const int w = t >> 5, lane = t & 31;
    const int bi = blockIdx.x;
    const int bh = bi >> 2, qt = bi & 3;
    const int b = bh >> 3, h = bh & 7;
    const int q0 = qt * 128;

    // flat contiguous copies (rows are 80B, globally contiguous)
    {
        const uint4* qsrc =
            (const uint4*)(g_q_split + ((size_t)bh * 512 + q0) * QKV_STRIDE);
        #pragma unroll
        for (int k = 0; k < 3; ++k) {
            int i = t + 256 * k;
            if (i < 640) ((uint4*)Qs)[i] = qsrc[i];
        }
        const uint4* ksrc =
            (const uint4*)(g_k_split + (size_t)bh * 512 * QKV_STRIDE);
        #pragma unroll
        for (int k = 0; k < 10; ++k)
            ((uint4*)Ks)[t + 256 * k] = ksrc[t + 256 * k];
        const uint4* vsrc =
            (const uint4*)(g_v_split + (size_t)bh * 512 * QKV_STRIDE);
        #pragma unroll
        for (int k = 0; k < 10; ++k)
            ((uint4*)Vs)[t + 256 * k] = vsrc[t + 256 * k];
    }
    __syncthreads();

    // Q fragments (single k16 step: D=16)
    unsigned aq_hi[4], aq_lo[4];
    {
        unsigned qaddr = smem_u32(Qs + (w * 16 + (lane & 15)) * QKV_STRIDE +
                                  (lane >> 4) * 8);
        ldmx4(aq_hi, qaddr);
        ldmx4(aq_lo, qaddr + 32);
    }

    float oacc[2][4];
    #pragma unroll
    for (int j = 0; j < 4; ++j) { oacc[0][j] = 0.f; oacc[1][j] = 0.f; }
    float rs0 = 0.f, rs1 = 0.f;

    const int nr0 = q0 + w * 16 + (lane >> 2);
    const int nr1 = nr0 + 8;
    const int nr0c = (nr0 < Nn) ? nr0 : 0;
    const int nr1c = (nr1 < Nn) ? nr1 : 0;

    for (int gt = 0; gt < 4; ++gt) {
        const int g0 = gt * 128;

        // ---- S = q.k over this 128-g chunk
        float sacc[16][4];
        #pragma unroll
        for (int i = 0; i < 16; ++i)
            sacc[i][0] = sacc[i][1] = sacc[i][2] = sacc[i][3] = 0.f;

        #pragma unroll
        for (int np = 0; np < 8; ++np) {
            unsigned ka = smem_u32(Ks + (g0 + np * 16 + (lane & 15)) *
                                            QKV_STRIDE +
                                   (lane >> 4) * 8);
            unsigned kh[4], kl[4];
            ldmx4(kh, ka);
            ldmx4(kl, ka + 32);
            mma16816(sacc[2 * np],     aq_hi, kh[0], kh[2]);
            mma16816(sacc[2 * np],     aq_hi, kl[0], kl[2]);
            mma16816(sacc[2 * np],     aq_lo, kh[0], kh[2]);
            mma16816(sacc[2 * np + 1], aq_hi, kh[1], kh[3]);
            mma16816(sacc[2 * np + 1], aq_hi, kl[1], kl[3]);
            mma16816(sacc[2 * np + 1], aq_lo, kh[1], kh[3]);
        }

        // masks for this chunk
        uint4 m0 = *(const uint4*)(g_maskbits + ((size_t)b * Nn + nr0c) * 16 +
                                   gt * 4);
        uint4 m1 = *(const uint4*)(g_maskbits + ((size_t)b * Nn + nr1c) * 16 +
                                   gt * 4);
        unsigned mw0[4] = {m0.x, m0.y, m0.z, m0.w};
        unsigned mw1[4] = {m1.x, m1.y, m1.z, m1.w};

        // ---- per-kk: softmax partial -> P frags -> AV MMAs
        #pragma unroll
        for (int kk = 0; kk < 8; ++kk) {
            unsigned pf_hi[4], pf_lo[4];
            #pragma unroll
            for (int half = 0; half < 2; ++half) {
                int ntile = 2 * kk + half;
                unsigned w0 = mw0[ntile >> 2];
                unsigned w1 = mw1[ntile >> 2];
                int bitb = (ntile & 3) * 8 + (lane & 3) * 2;
                float p00 = exp2f(sacc[ntile][0]);
                float p01 = exp2f(sacc[ntile][1]);
                float p10 = exp2f(sacc[ntile][2]);
                float p11 = exp2f(sacc[ntile][3]);
                p00 = ((w0 >> bitb) & 1u) ? p00 : 0.f;
                p01 = ((w0 >> (bitb + 1)) & 1u) ? p01 : 0.f;
                p10 = ((w1 >> bitb) & 1u) ? p10 : 0.f;
                p11 = ((w1 >> (bitb + 1)) & 1u) ? p11 : 0.f;
                rs0 += p00 + p01;
                rs1 += p10 + p11;
                __nv_bfloat162 h0 = __floats2bfloat162_rn(p00, p01);
                __nv_bfloat162 h1 = __floats2bfloat162_rn(p10, p11);
                float2 hf0 = __bfloat1622float2(h0);
                float2 hf1 = __bfloat1622float2(h1);
                pf_hi[2 * half + 0] = *(unsigned*)&h0;
                pf_hi[2 * half + 1] = *(unsigned*)&h1;
                pf_lo[2 * half + 0] = pack_bf2(p00 - hf0.x, p01 - hf0.y);
                pf_lo[2 * half + 1] = pack_bf2(p10 - hf1.x, p11 - hf1.y);
            }
            unsigned va = smem_u32(Vs + (g0 + kk * 16 + (lane & 15)) *
                                            QKV_STRIDE +
                                   (lane >> 4) * 8);
            unsigned vh[4], vl[4];
            ldmx4t(vh, va);
            ldmx4t(vl, va + 32);
            mma16816(oacc[0], pf_hi, vh[0], vh[1]);
            mma16816(oacc[0], pf_hi, vl[0], vl[1]);
            mma16816(oacc[0], pf_lo, vh[0], vh[1]);
            mma16816(oacc[1], pf_hi, vh[2], vh[3]);
            mma16816(oacc[1], pf_hi, vl[2], vl[3]);
            mma16816(oacc[1], pf_lo, vh[2], vh[3]);
        }
    }

    // row sums within quad (row fixed by lane>>2)
    rs0 += __shfl_xor_sync(0xffffffffu, rs0, 1);
    rs0 += __shfl_xor_sync(0xffffffffu, rs0, 2);
    rs1 += __shfl_xor_sync(0xffffffffu, rs1, 1);
    rs1 += __shfl_xor_sync(0xffffffffu, rs1, 2);
    float inv0 = __fdividef(1.0f, rs0);
    float inv1 = __fdividef(1.0f, rs1);

    const int d0 = (lane & 3) * 2;
    if (nr0 < Nn) {
        float* orow = g_att + ((size_t)b * Nn + nr0) * 128 + h * 16;
        *(float2*)(orow + d0) =
            make_float2(oacc[0][0] * inv0, oacc[0][1] * inv0);
        *(float2*)(orow + 8 + d0) =
            make_float2(oacc[1][0] * inv0, oacc[1][1] * inv0);
    }
    if (nr1 < Nn) {
        float* orow = g_att + ((size_t)b * Nn + nr1) * 128 + h * 16;
        *(float2*)(orow + d0) =
            make_float2(oacc[0][2] * inv1, oacc[0][3] * inv1);
        *(float2*)(orow + 8 + d0) =
            make_float2(oacc[1][2] * inv1, oacc[1][3] * inv1);
    }
}

// ---------------------------------------------------------------------------
// Combine: mh = att @ Wc^T + bc -> split bf16 directly
// ---------------------------------------------------------------------------
__global__ void __launch_bounds__(256, 2)
combine_kernel(const float* __restrict__ Wc, const float* __restrict__ bc) {
    proj_body(g_att, Wc, nullptr, nullptr, bc, nullptr, 1.0f, 2,
              blockIdx.x * 64);
}

// ---------------------------------------------------------------------------
// Pointer stage via HMMA (unchanged from v4; near its MUFU roofline).
// ---------------------------------------------------------------------------
#define AS_STRIDE 264
#define PTR_SMEM (128 * AS_STRIDE * 2 * 2 + 512)

__global__ void __launch_bounds__(256, 1)
pointer_mma_kernel(float* __restrict__ out) {
    extern __shared__ char smem[];
    __nv_bfloat16* As = (__nv_bfloat16*)smem;
    __nv_bfloat16* Bs = As + 128 * AS_STRIDE;
    float* rsum = (float*)(Bs + 128 * AS_STRIDE);

    const int t = threadIdx.x;
    const int w = t >> 5, lane = t & 31;
    const int b = blockIdx.x >> 2;
    const int nt4 = blockIdx.x & 3;
    const int n0 = nt4 * 128;

    {
        const uint4* src =
            (const uint4*)(g_mh_split + ((size_t)(b * 512 + n0)) * 256);
        #pragma unroll
        for (int k = 0; k < 16; ++k) {
            int i4 = t + 256 * k;
            int row = i4 >> 5, c8 = i4 & 31;
            *(uint4*)(As + row * AS_STRIDE + c8 * 8) = src[i4];
        }
    }
    __syncthreads();

    unsigned af_hi[8][4], af_lo[8][4];
    {
        unsigned rowa = w * 16 + (lane & 15);
        unsigned colbase = (lane >> 4) * 8;
        #pragma unroll
        for (int kk = 0; kk < 8; ++kk) {
            unsigned addr = smem_u32(As + rowa * AS_STRIDE + colbase + kk * 16);
            ldmx4(af_hi[kk], addr);
            ldmx4(af_lo[kk], addr + 128 * 2);
        }
    }

    const float C1 = 0.08838834764831845f * 2.0f * 1.4426950408889634f;
    const float C2 = 10.0f * 1.4426950408889634f;

    const int nr0 = n0 + w * 16 + (lane >> 2);
    const int nr1 = nr0 + 8;
    const int nr0c = (nr0 < Nn) ? nr0 : 0;
    const int nr1c = (nr1 < Nn) ? nr1 : 0;
    float rs0 = 0.f, rs1 = 0.f;

    for (int gt = 0; gt < 4; ++gt) {
        const int g0 = gt * 128;
        __syncthreads();
        {
            const uint4* src =
                (const uint4*)(g_enc_split + ((size_t)(b * 512 + g0)) * 256);
            #pragma unroll
            for (int k = 0; k < 16; ++k) {
                int i4 = t + 256 * k;
                int row = i4 >> 5, c8 = i4 & 31;
                *(uint4*)(Bs + row * AS_STRIDE + c8 * 8) = src[i4];
            }
        }
        __syncthreads();

        float acc[16][4];
        #pragma unroll
        for (int i = 0; i < 16; ++i)
            acc[i][0] = acc[i][1] = acc[i][2] = acc[i][3] = 0.f;

        unsigned browb = (lane & 15);
        unsigned bcolb = (lane >> 4) * 8;
        #pragma unroll
        for (int kk = 0; kk < 8; ++kk) {
            #pragma unroll
            for (int np = 0; np < 8; ++np) {
                unsigned baddr = smem_u32(Bs + (np * 16 + browb) * AS_STRIDE +
                                          bcolb + kk * 16);
                unsigned bh[4], bl[4];
                ldmx4(bh, baddr);
                ldmx4(bl, baddr + 128 * 2);
                mma16816(acc[2 * np],     af_hi[kk], bh[0], bh[2]);
                mma16816(acc[2 * np + 1], af_hi[kk], bh[1], bh[3]);
                mma16816(acc[2 * np],     af_hi[kk], bl[0], bl[2]);
                mma16816(acc[2 * np + 1], af_hi[kk], bl[1], bl[3]);
                mma16816(acc[2 * np],     af_lo[kk], bh[0], bh[2]);
                mma16816(acc[2 * np + 1], af_lo[kk], bh[1], bh[3]);
            }
        }

        uint4 m0 = *(const uint4*)(g_maskbits + ((size_t)b * Nn + nr0c) * 16 +
                                   gt * 4);
        uint4 m1 = *(const uint4*)(g_maskbits + ((size_t)b * Nn + nr1c) * 16 +
                                   gt * 4);
        unsigned mw0[4] = {m0.x, m0.y, m0.z, m0.w};
        unsigned mw1[4] = {m1.x, m1.y, m1.z, m1.w};

        #pragma unroll
        for (int ntile = 0; ntile < 16; ++ntile) {
            unsigned w0 = mw0[ntile >> 2];
            unsigned w1 = mw1[ntile >> 2];
            int bitb = (ntile & 3) * 8 + (lane & 3) * 2;
            float p00, p01, p10, p11;
            {
                float u = exp2f(acc[ntile][0] * C1);
                p00 = exp2f(C2 * (1.0f - __fdividef(2.0f, u + 1.0f)));
            }
            {
                float u = exp2f(acc[ntile][1] * C1);
                p01 = exp2f(C2 * (1.0f - __fdividef(2.0f, u + 1.0f)));
            }
            {
                float u = exp2f(acc[ntile][2] * C1);
                p10 = exp2f(C2 * (1.0f - __fdividef(2.0f, u + 1.0f)));
            }
            {
                float u = exp2f(acc[ntile][3] * C1);
                p11 = exp2f(C2 * (1.0f - __fdividef(2.0f, u + 1.0f)));
            }
            p00 = ((w0 >> bitb) & 1u) ? p00 : 0.f;
            p01 = ((w0 >> (bitb + 1)) & 1u) ? p01 : 0.f;
            p10 = ((w1 >> bitb) & 1u) ? p10 : 0.f;
            p11 = ((w1 >> (bitb + 1)) & 1u) ? p11 : 0.f;
            rs0 += p00 + p01;
            rs1 += p10 + p11;
            int g = g0 + ntile * 8 + (lane & 3) * 2;
            if (g < Nn) {
                if (nr0 < Nn)
                    *(float2*)(out + ((size_t)b * Nn + nr0) * Nn + g) =
                        make_float2(p00, p01);
                if (nr1 < Nn)
                    *(float2*)(out + ((size_t)b * Nn + nr1) * Nn + g) =
                        make_float2(p10, p11);
            }
        }
    }

    rs0 += __shfl_xor_sync(0xffffffffu, rs0, 1);
    rs0 += __shfl_xor_sync(0xffffffffu, rs0, 2);
    rs1 += __shfl_xor_sync(0xffffffffu, rs1, 1);
    rs1 += __shfl_xor_sync(0xffffffffu, rs1, 2);
    if ((lane & 3) == 0) {
        rsum[w * 16 + (lane >> 2)] = rs0;
        rsum[w * 16 + (lane >> 2) + 8] = rs1;
    }
    __syncthreads();

    for (int i4 = t; i4 < 128 * 125; i4 += 256) {
        int row = i4 / 125, c4 = i4 - row * 125;
        int n = n0 + row;
        if (n < Nn) {
            float inv = __fdividef(1.0f, rsum[row]);
            float4* po = (float4*)(out + ((size_t)b * Nn + n) * Nn) + c4;
            float4 p = *po;
            p.x *= inv; p.y *= inv; p.z *= inv; p.w *= inv;
            *po = p;
        }
    }
}

// ---------------------------------------------------------------------------
// Launch
// ---------------------------------------------------------------------------
extern "C" void kernel_launch(void* const* d_in, const int* in_sizes, int n_in,
                              void* d_out, int out_size) {
    const float* enc_nodes = (const float*)d_in[0];
    const float* enc_first = (const float*)d_in[1];
    const float* enc_last  = (const float*)d_in[2];
    const float* mask      = (const float*)d_in[3];
    const float* Wq_first  = (const float*)d_in[4];
    const float* Wq_last   = (const float*)d_in[5];
    const float* Wk        = (const float*)d_in[6];
    const float* Wv        = (const float*)d_in[7];
    const float* Wc        = (const float*)d_in[8];
    const float* bc        = (const float*)d_in[9];
    float* out = (float*)d_out;

    const int PROJ_SMEM = (64 * 128 + 128 * 132) * 4;   // 100352

    static int configured = 0;
    if (!configured) {
        cudaFuncSetAttribute(stageA_kernel,
            cudaFuncAttributeMaxDynamicSharedMemorySize, PROJ_SMEM);
        cudaFuncSetAttribute(attn_mma_kernel,
            cudaFuncAttributeMaxDynamicSharedMemorySize, ATT_SMEM);
        cudaFuncSetAttribute(combine_kernel,
            cudaFuncAttributeMaxDynamicSharedMemorySize, PROJ_SMEM);
        cudaFuncSetAttribute(pointer_mma_kernel,
            cudaFuncAttributeMaxDynamicSharedMemorySize, PTR_SMEM);
        configured = 1;
    }

    // A) q/k/v projections (split bf16) + maskbits + enc split
    stageA_kernel<<<1814, 256, PROJ_SMEM>>>(enc_nodes, enc_first, enc_last,
                                            mask, Wq_first, Wq_last, Wk, Wv);
    // B) attention via HMMA
    attn_mma_kernel<<<Bb * Hh * 4, 256, ATT_SMEM>>>();
    // C) combine -> mh split bf16
    combine_kernel<<<500, 256, PROJ_SMEM>>>(Wc, bc);
    // D) pointer attention via HMMA
    pointer_mma_kernel<<<Bb * 4, 256, PTR_SMEM>>>(out);

    (void)in_sizes; (void)n_in; (void)out_size;
}

// round 6
// speedup vs baseline: 2.8120x; 1.0502x over previous
#include <cuda_runtime.h>
#include <cuda_bf16.h>
#include <math.h>

// ---------------------------------------------------------------------------
// POMO decoder v6 — HMMA split-bf16 attention + pointer (occupancy-fixed);
// f32x2 projections. B=64, N=500, E=128, H=8, D=16
// ---------------------------------------------------------------------------

#define Bb 64
#define Nn 500
#define Hh 8
#define QKV_STRIDE 40   // [hi 16 | lo 16 | pad 8] bf16 => 80B rows (LDSM clean)

typedef unsigned long long ull;

__device__ float g_att[Bb * Nn * 128];
__device__ unsigned g_maskbits[Bb * Nn * 16];
// split bf16: q/k/v per (b,h): [512 rows][40], q pre-scaled by log2e/4
__device__ __nv_bfloat16 g_q_split[Bb * Hh * 512 * QKV_STRIDE];
__device__ __nv_bfloat16 g_k_split[Bb * Hh * 512 * QKV_STRIDE];
__device__ __nv_bfloat16 g_v_split[Bb * Hh * 512 * QKV_STRIDE];
// split bf16: [b][row 512][hi 128 | lo 128]
__device__ __nv_bfloat16 g_mh_split[Bb * 512 * 256];
__device__ __nv_bfloat16 g_enc_split[Bb * 512 * 256];

// ---- f32x2 helpers ---------------------------------------------------------
__device__ __forceinline__ ull fma2(ull a, ull b, ull c) {
    ull d;
    asm("fma.rn.f32x2 %0, %1, %2, %3;" : "=l"(d) : "l"(a), "l"(b), "l"(c));
    return d;
}
__device__ __forceinline__ float2 unpack2(ull a) {
    float2 f;
    asm("mov.b64 {%0, %1}, %2;" : "=f"(f.x), "=f"(f.y) : "l"(a));
    return f;
}

__device__ __forceinline__ unsigned smem_u32(const void* p) {
    unsigned a;
    asm("{ .reg .u64 t; cvta.to.shared.u64 t, %1; cvt.u32.u64 %0, t; }"
        : "=r"(a) : "l"(p));
    return a;
}

// ---- mma.sync / ldmatrix helpers -------------------------------------------
__device__ __forceinline__ void ldmx4(unsigned* r, unsigned addr) {
    asm volatile(
        "ldmatrix.sync.aligned.m8n8.x4.shared.b16 {%0,%1,%2,%3}, [%4];"
        : "=r"(r[0]), "=r"(r[1]), "=r"(r[2]), "=r"(r[3]) : "r"(addr));
}
__device__ __forceinline__ void ldmx4t(unsigned* r, unsigned addr) {
    asm volatile(
        "ldmatrix.sync.aligned.m8n8.x4.trans.shared.b16 {%0,%1,%2,%3}, [%4];"
        : "=r"(r[0]), "=r"(r[1]), "=r"(r[2]), "=r"(r[3]) : "r"(addr));
}
__device__ __forceinline__ void mma16816(float* c, const unsigned* a,
                                         unsigned b0, unsigned b1) {
    asm volatile(
        "mma.sync.aligned.m16n8k16.row.col.f32.bf16.bf16.f32 "
        "{%0,%1,%2,%3}, {%4,%5,%6,%7}, {%8,%9}, {%0,%1,%2,%3};"
        : "+f"(c[0]), "+f"(c[1]), "+f"(c[2]), "+f"(c[3])
        : "r"(a[0]), "r"(a[1]), "r"(a[2]), "r"(a[3]), "r"(b0), "r"(b1));
}
__device__ __forceinline__ unsigned pack_bf2(float x, float y) {
    __nv_bfloat162 h = __floats2bfloat162_rn(x, y);
    return *(unsigned*)&h;
}

// ---------------------------------------------------------------------------
// Projection body (f32x2). mode 1: split-bf16 heads layout (q/k/v, scale).
// mode 2: split-bf16 mh layout.
// ---------------------------------------------------------------------------
__device__ __forceinline__ void proj_body(const float* __restrict__ A0,
                                          const float* __restrict__ W0,
                                          const float* __restrict__ A1,
                                          const float* __restrict__ W1,
                                          const float* __restrict__ bias,
                                          __nv_bfloat16* __restrict__ outb,
                                          float oscale, int mode, int m0) {
    extern __shared__ float sh[];
    float* Xs = sh;              // [64][128]
    float* Ws = sh + 64 * 128;   // [128][132] K-major, padded

    const int t = threadIdx.x;
    const int ty = t >> 5, tx = t & 31;

    ull acc[8][4];
    #pragma unroll
    for (int i = 0; i < 8; ++i)
        #pragma unroll
        for (int j = 0; j < 4; ++j) acc[i][j] = 0ULL;

    const int npass = (A1 != nullptr) ? 2 : 1;
    for (int pass = 0; pass < npass; ++pass) {
        const float* A = pass ? A1 : A0;
        const float* W = pass ? W1 : W0;
        if (pass) __syncthreads();
        const float4* A4 = (const float4*)(A + (size_t)m0 * 128);
        #pragma unroll
        for (int k = 0; k < 8; ++k)
            ((float4*)Xs)[t + 256 * k] = A4[t + 256 * k];
        const float4* W4 = (const float4*)W;
        #pragma unroll
        for (int k = 0; k < 16; ++k) {
            int i4 = t + 256 * k;
            int f = i4 >> 5, e4 = i4 & 31;
            *(float4*)(Ws + f * 132 + e4 * 4) = W4[i4];
        }
        __syncthreads();

        for (int e0 = 0; e0 < 128; e0 += 4) {
            ulonglong2 wv[4];
            #pragma unroll
            for (int j = 0; j < 4; ++j)
                wv[j] = *(const ulonglong2*)(Ws + (tx + 32 * j) * 132 + e0);
            #pragma unroll
            for (int i = 0; i < 8; ++i) {
                ulonglong2 xv =
                    *(const ulonglong2*)(Xs + (ty * 8 + i) * 128 + e0);
                #pragma unroll
                for (int j = 0; j < 4; ++j) {
                    acc[i][j] = fma2(xv.x, wv[j].x, acc[i][j]);
                    acc[i][j] = fma2(xv.y, wv[j].y, acc[i][j]);
                }
            }
        }
    }

    float bb[4] = {0.f, 0.f, 0.f, 0.f};
    if (bias) {
        #pragma unroll
        for (int j = 0; j < 4; ++j) bb[j] = bias[tx + 32 * j];
    }
    #pragma unroll
    for (int i = 0; i < 8; ++i) {
        int m = m0 + ty * 8 + i;
        int b = m / Nn, n = m - b * Nn;
        #pragma unroll
        for (int j = 0; j < 4; ++j) {
            int f = tx + 32 * j;
            float2 s = unpack2(acc[i][j]);
            float r = (s.x + s.y + bb[j]) * oscale;
            __nv_bfloat16 hi = __float2bfloat16(r);
            float lo = r - __bfloat162float(hi);
            if (mode == 1) {
                int h = f >> 4, d = f & 15;
                size_t base =
                    ((size_t)((b * Hh + h) * 512 + n)) * QKV_STRIDE + d;
                outb[base] = hi;
                outb[base + 16] = __float2bfloat16(lo);
            } else {
                size_t base = ((size_t)(b * 512 + n)) * 256;
                g_mh_split[base + f] = hi;
                g_mh_split[base + 128 + f] = __float2bfloat16(lo);
            }
        }
    }
}

// ---------------------------------------------------------------------------
// Stage A: fused q/k/v projections + maskbits + enc split
// ---------------------------------------------------------------------------
__global__ void __launch_bounds__(256, 2)
stageA_kernel(const float* __restrict__ enc_nodes,
              const float* __restrict__ enc_first,
              const float* __restrict__ enc_last,
              const float* __restrict__ mask,
              const float* __restrict__ Wqf, const float* __restrict__ Wql,
              const float* __restrict__ Wk, const float* __restrict__ Wv) {
    const float QS = 1.4426950408889634f * 0.25f;  // log2e / sqrt(D)
    int bi = blockIdx.x;
    if (bi < 500) {
        proj_body(enc_first, Wqf, enc_last, Wql, nullptr, g_q_split, QS, 1,
                  bi * 64);
    } else if (bi < 1000) {
        proj_body(enc_nodes, Wk, nullptr, nullptr, nullptr, g_k_split, 1.0f, 1,
                  (bi - 500) * 64);
    } else if (bi < 1500) {
        proj_body(enc_nodes, Wv, nullptr, nullptr, nullptr, g_v_split, 1.0f, 1,
                  (bi - 1000) * 64);
    } else if (bi < 1750) {
        // maskbits: 128 rows per block
        int t = threadIdx.x;
        int wid = t >> 5, lane = t & 31;
        int rowbase = (bi - 1500) * 128 + wid * 16;
        for (int rr = 0; rr < 16; ++rr) {
            int row = rowbase + rr;
            const float* mrow = mask + (size_t)row * Nn;
            unsigned* brow = g_maskbits + (size_t)row * 16;
            #pragma unroll
            for (int w = 0; w < 16; ++w) {
                int g = w * 32 + lane;
                float v = (g < Nn) ? mrow[g] : -1e9f;
                unsigned bal = __ballot_sync(0xffffffffu, v > -1.0f);
                if (lane == 0) brow[w] = bal;
            }
        }
    } else {
        // enc split: one batch per block (64 blocks)
        int b = bi - 1750;
        int t = threadIdx.x;
        const float4* src = (const float4*)(enc_nodes + (size_t)b * Nn * 128);
        for (int i4 = t; i4 < Nn * 32; i4 += 256) {
            int n = i4 >> 5, e4 = i4 & 31;
            float4 v = src[i4];
            __nv_bfloat162 h01 = __floats2bfloat162_rn(v.x, v.y);
            __nv_bfloat162 h23 = __floats2bfloat162_rn(v.z, v.w);
            float2 hf01 = __bfloat1622float2(h01);
            float2 hf23 = __bfloat1622float2(h23);
            __nv_bfloat162 l01 =
                __floats2bfloat162_rn(v.x - hf01.x, v.y - hf01.y);
            __nv_bfloat162 l23 =
                __floats2bfloat162_rn(v.z - hf23.x, v.w - hf23.y);
            __nv_bfloat16* dst =
                g_enc_split + ((size_t)(b * 512 + n)) * 256 + e4 * 4;
            *(__nv_bfloat162*)(dst) = h01;
            *(__nv_bfloat162*)(dst + 2) = h23;
            *(__nv_bfloat162*)(dst + 128) = l01;
            *(__nv_bfloat162*)(dst + 130) = l23;
        }
    }
}

// ---------------------------------------------------------------------------
// Attention via HMMA (unchanged from v5, passing)
// ---------------------------------------------------------------------------
#define ATT_SMEM ((128 + 512 + 512) * QKV_STRIDE * 2)

__global__ void __launch_bounds__(256, 2)
attn_mma_kernel() {
    extern __shared__ char smem[];
    __nv_bfloat16* Qs = (__nv_bfloat16*)smem;
    __nv_bfloat16* Ks = Qs + 128 * QKV_STRIDE;
    __nv_bfloat16* Vs = Ks + 512 * QKV_STRIDE;

    const int t = threadIdx.x;
    const int w = t >> 5, lane = t & 31;
    const int bi = blockIdx.x;
    const int bh = bi >> 2, qt = bi & 3;
    const int b = bh >> 3, h = bh & 7;
    const int q0 = qt * 128;

    {
        const uint4* qsrc =
            (const uint4*)(g_q_split + ((size_t)bh * 512 + q0) * QKV_STRIDE);
        #pragma unroll
        for (int k = 0; k < 3; ++k) {
            int i = t + 256 * k;
            if (i < 640) ((uint4*)Qs)[i] = qsrc[i];
        }
        const uint4* ksrc =
            (const uint4*)(g_k_split + (size_t)bh * 512 * QKV_STRIDE);
        #pragma unroll
        for (int k = 0; k < 10; ++k)
            ((uint4*)Ks)[t + 256 * k] = ksrc[t + 256 * k];
        const uint4* vsrc =
            (const uint4*)(g_v_split + (size_t)bh * 512 * QKV_STRIDE);
        #pragma unroll
        for (int k = 0; k < 10; ++k)
            ((uint4*)Vs)[t + 256 * k] = vsrc[t + 256 * k];
    }
    __syncthreads();

    unsigned aq_hi[4], aq_lo[4];
    {
        unsigned qaddr = smem_u32(Qs + (w * 16 + (lane & 15)) * QKV_STRIDE +
                                  (lane >> 4) * 8);
        ldmx4(aq_hi, qaddr);
        ldmx4(aq_lo, qaddr + 32);
    }

    float oacc[2][4];
    #pragma unroll
    for (int j = 0; j < 4; ++j) { oacc[0][j] = 0.f; oacc[1][j] = 0.f; }
    float rs0 = 0.f, rs1 = 0.f;

    const int nr0 = q0 + w * 16 + (lane >> 2);
    const int nr1 = nr0 + 8;
    const int nr0c = (nr0 < Nn) ? nr0 : 0;
    const int nr1c = (nr1 < Nn) ? nr1 : 0;

    for (int gt = 0; gt < 4; ++gt) {
        const int g0 = gt * 128;

        float sacc[16][4];
        #pragma unroll
        for (int i = 0; i < 16; ++i)
            sacc[i][0] = sacc[i][1] = sacc[i][2] = sacc[i][3] = 0.f;

        #pragma unroll
        for (int np = 0; np < 8; ++np) {
            unsigned ka = smem_u32(Ks + (g0 + np * 16 + (lane & 15)) *
                                            QKV_STRIDE +
                                   (lane >> 4) * 8);
            unsigned kh[4], kl[4];
            ldmx4(kh, ka);
            ldmx4(kl, ka + 32);
            mma16816(sacc[2 * np],     aq_hi, kh[0], kh[2]);
            mma16816(sacc[2 * np],     aq_hi, kl[0], kl[2]);
            mma16816(sacc[2 * np],     aq_lo, kh[0], kh[2]);
            mma16816(sacc[2 * np + 1], aq_hi, kh[1], kh[3]);
            mma16816(sacc[2 * np + 1], aq_hi, kl[1], kl[3]);
            mma16816(sacc[2 * np + 1], aq_lo, kh[1], kh[3]);
        }

        uint4 m0 = *(const uint4*)(g_maskbits + ((size_t)b * Nn + nr0c) * 16 +
                                   gt * 4);
        uint4 m1 = *(const uint4*)(g_maskbits + ((size_t)b * Nn + nr1c) * 16 +
                                   gt * 4);
        unsigned mw0[4] = {m0.x, m0.y, m0.z, m0.w};
        unsigned mw1[4] = {m1.x, m1.y, m1.z, m1.w};

        #pragma unroll
        for (int kk = 0; kk < 8; ++kk) {
            unsigned pf_hi[4], pf_lo[4];
            #pragma unroll
            for (int half = 0; half < 2; ++half) {
                int ntile = 2 * kk + half;
                unsigned w0 = mw0[ntile >> 2];
                unsigned w1 = mw1[ntile >> 2];
                int bitb = (ntile & 3) * 8 + (lane & 3) * 2;
                float p00 = exp2f(sacc[ntile][0]);
                float p01 = exp2f(sacc[ntile][1]);
                float p10 = exp2f(sacc[ntile][2]);
                float p11 = exp2f(sacc[ntile][3]);
                p00 = ((w0 >> bitb) & 1u) ? p00 : 0.f;
                p01 = ((w0 >> (bitb + 1)) & 1u) ? p01 : 0.f;
                p10 = ((w1 >> bitb) & 1u) ? p10 : 0.f;
                p11 = ((w1 >> (bitb + 1)) & 1u) ? p11 : 0.f;
                rs0 += p00 + p01;
                rs1 += p10 + p11;
                __nv_bfloat162 h0 = __floats2bfloat162_rn(p00, p01);
                __nv_bfloat162 h1 = __floats2bfloat162_rn(p10, p11);
                float2 hf0 = __bfloat1622float2(h0);
                float2 hf1 = __bfloat1622float2(h1);
                pf_hi[2 * half + 0] = *(unsigned*)&h0;
                pf_hi[2 * half + 1] = *(unsigned*)&h1;
                pf_lo[2 * half + 0] = pack_bf2(p00 - hf0.x, p01 - hf0.y);
                pf_lo[2 * half + 1] = pack_bf2(p10 - hf1.x, p11 - hf1.y);
            }
            unsigned va = smem_u32(Vs + (g0 + kk * 16 + (lane & 15)) *
                                            QKV_STRIDE +
                                   (lane >> 4) * 8);
            unsigned vh[4], vl[4];
            ldmx4t(vh, va);
            ldmx4t(vl, va + 32);
            mma16816(oacc[0], pf_hi, vh[0], vh[1]);
            mma16816(oacc[0], pf_hi, vl[0], vl[1]);
            mma16816(oacc[0], pf_lo, vh[0], vh[1]);
            mma16816(oacc[1], pf_hi, vh[2], vh[3]);
            mma16816(oacc[1], pf_hi, vl[2], vl[3]);
            mma16816(oacc[1], pf_lo, vh[2], vh[3]);
        }
    }

    rs0 += __shfl_xor_sync(0xffffffffu, rs0, 1);
    rs0 += __shfl_xor_sync(0xffffffffu, rs0, 2);
    rs1 += __shfl_xor_sync(0xffffffffu, rs1, 1);
    rs1 += __shfl_xor_sync(0xffffffffu, rs1, 2);
    float inv0 = __fdividef(1.0f, rs0);
    float inv1 = __fdividef(1.0f, rs1);

    const int d0 = (lane & 3) * 2;
    if (nr0 < Nn) {
        float* orow = g_att + ((size_t)b * Nn + nr0) * 128 + h * 16;
        *(float2*)(orow + d0) =
            make_float2(oacc[0][0] * inv0, oacc[0][1] * inv0);
        *(float2*)(orow + 8 + d0) =
            make_float2(oacc[1][0] * inv0, oacc[1][1] * inv0);
    }
    if (nr1 < Nn) {
        float* orow = g_att + ((size_t)b * Nn + nr1) * 128 + h * 16;
        *(float2*)(orow + d0) =
            make_float2(oacc[0][2] * inv1, oacc[0][3] * inv1);
        *(float2*)(orow + 8 + d0) =
            make_float2(oacc[1][2] * inv1, oacc[1][3] * inv1);
    }
}

// ---------------------------------------------------------------------------
// Combine: mh = att @ Wc^T + bc -> split bf16 directly
// ---------------------------------------------------------------------------
__global__ void __launch_bounds__(256, 2)
combine_kernel(const float* __restrict__ Wc, const float* __restrict__ bc) {
    proj_body(g_att, Wc, nullptr, nullptr, bc, nullptr, 1.0f, 2,
              blockIdx.x * 64);
}

// ---------------------------------------------------------------------------
// Pointer via HMMA v6 — occupancy-optimized.
// Block = (b, 64-row tile): grid 512. 8 warps: (w&3)=row stripe (m16),
// (w>>2)=g half (n64). acc[8][4]=32 regs; A hi/lo frags cached (64 regs).
// smem: As 64x264 + Bs 128x264 + rsum[2][64] ~= 102 KB -> 2 blocks/SM.
// ---------------------------------------------------------------------------
#define AS_STRIDE 264
#define PTR_SMEM ((64 + 128) * AS_STRIDE * 2 + 512)

__global__ void __launch_bounds__(256, 2)
pointer_mma_kernel(float* __restrict__ out) {
    extern __shared__ char smem[];
    __nv_bfloat16* As = (__nv_bfloat16*)smem;                 // [64][264]
    __nv_bfloat16* Bs = As + 64 * AS_STRIDE;                  // [128][264]
    float* rsum = (float*)(Bs + 128 * AS_STRIDE);             // [2][64]

    const int t = threadIdx.x;
    const int w = t >> 5, lane = t & 31;
    const int b = blockIdx.x >> 3;
    const int nt = blockIdx.x & 7;
    const int n0 = nt * 64;
    const int wrow = (w & 3) * 16;   // warp's row stripe within 64
    const int half = w >> 2;         // warp's g half (0/1) within 128-g tile

    // fill A tile (64 rows of mh_split)
    {
        const uint4* src =
            (const uint4*)(g_mh_split + ((size_t)(b * 512 + n0)) * 256);
        #pragma unroll
        for (int k = 0; k < 8; ++k) {
            int i4 = t + 256 * k;
            int row = i4 >> 5, c8 = i4 & 31;
            *(uint4*)(As + row * AS_STRIDE + c8 * 8) = src[i4];
        }
    }
    __syncthreads();

    // cache A fragments hi+lo (row stripe shared by both halves' warps)
    unsigned af_hi[8][4], af_lo[8][4];
    {
        unsigned rowa = wrow + (lane & 15);
        unsigned colbase = (lane >> 4) * 8;
        #pragma unroll
        for (int kk = 0; kk < 8; ++kk) {
            unsigned addr = smem_u32(As + rowa * AS_STRIDE + colbase + kk * 16);
            ldmx4(af_hi[kk], addr);
            ldmx4(af_lo[kk], addr + 128 * 2);
        }
    }

    const float C1 = 0.08838834764831845f * 2.0f * 1.4426950408889634f;
    const float C2 = 10.0f * 1.4426950408889634f;

    const int nr0 = n0 + wrow + (lane >> 2);
    const int nr1 = nr0 + 8;
    const int nr0c = (nr0 < Nn) ? nr0 : 0;
    const int nr1c = (nr1 < Nn) ? nr1 : 0;
    float rs0 = 0.f, rs1 = 0.f;

    for (int gt = 0; gt < 4; ++gt) {
        const int g0 = gt * 128;
        __syncthreads();
        {
            const uint4* src =
                (const uint4*)(g_enc_split + ((size_t)(b * 512 + g0)) * 256);
            #pragma unroll
            for (int k = 0; k < 16; ++k) {
                int i4 = t + 256 * k;
                int row = i4 >> 5, c8 = i4 & 31;
                *(uint4*)(Bs + row * AS_STRIDE + c8 * 8) = src[i4];
            }
        }
        __syncthreads();

        float acc[8][4];
        #pragma unroll
        for (int i = 0; i < 8; ++i)
            acc[i][0] = acc[i][1] = acc[i][2] = acc[i][3] = 0.f;

        unsigned browb = half * 64 + (lane & 15);
        unsigned bcolb = (lane >> 4) * 8;
        #pragma unroll
        for (int kk = 0; kk < 8; ++kk) {
            #pragma unroll
            for (int np = 0; np < 4; ++np) {
                unsigned baddr = smem_u32(Bs + (np * 16 + browb) * AS_STRIDE +
                                          bcolb + kk * 16);
                unsigned bh[4], bl[4];
                ldmx4(bh, baddr);
                ldmx4(bl, baddr + 128 * 2);
                mma16816(acc[2 * np],     af_hi[kk], bh[0], bh[2]);
                mma16816(acc[2 * np + 1], af_hi[kk], bh[1], bh[3]);
                mma16816(acc[2 * np],     af_hi[kk], bl[0], bl[2]);
                mma16816(acc[2 * np + 1], af_hi[kk], bl[1], bl[3]);
                mma16816(acc[2 * np],     af_lo[kk], bh[0], bh[2]);
                mma16816(acc[2 * np + 1], af_lo[kk], bh[1], bh[3]);
            }
        }

        // epilogue for this g-tile (warp covers g in [g0+half*64, +64))
        uint4 m0 = *(const uint4*)(g_maskbits + ((size_t)b * Nn + nr0c) * 16 +
                                   gt * 4);
        uint4 m1 = *(const uint4*)(g_maskbits + ((size_t)b * Nn + nr1c) * 16 +
                                   gt * 4);
        unsigned mw0[4] = {m0.x, m0.y, m0.z, m0.w};
        unsigned mw1[4] = {m1.x, m1.y, m1.z, m1.w};

        #pragma unroll
        for (int ntile = 0; ntile < 8; ++ntile) {
            int widx = half * 2 + (ntile >> 2);
            unsigned w0 = mw0[widx];
            unsigned w1 = mw1[widx];
            int bitb = (ntile & 3) * 8 + (lane & 3) * 2;
            float p00, p01, p10, p11;
            {
                float u = exp2f(acc[ntile][0] * C1);
                p00 = exp2f(C2 * (1.0f - __fdividef(2.0f, u + 1.0f)));
            }
            {
                float u = exp2f(acc[ntile][1] * C1);
                p01 = exp2f(C2 * (1.0f - __fdividef(2.0f, u + 1.0f)));
            }
            {
                float u = exp2f(acc[ntile][2] * C1);
                p10 = exp2f(C2 * (1.0f - __fdividef(2.0f, u + 1.0f)));
            }
            {
                float u = exp2f(acc[ntile][3] * C1);
                p11 = exp2f(C2 * (1.0f - __fdividef(2.0f, u + 1.0f)));
            }
            p00 = ((w0 >> bitb) & 1u) ? p00 : 0.f;
            p01 = ((w0 >> (bitb + 1)) & 1u) ? p01 : 0.f;
            p10 = ((w1 >> bitb) & 1u) ? p10 : 0.f;
            p11 = ((w1 >> (bitb + 1)) & 1u) ? p11 : 0.f;
            rs0 += p00 + p01;
            rs1 += p10 + p11;
            int g = g0 + half * 64 + ntile * 8 + (lane & 3) * 2;
            if (g < Nn) {
                if (nr0 < Nn)
                    *(float2*)(out + ((size_t)b * Nn + nr0) * Nn + g) =
                        make_float2(p00, p01);
                if (nr1 < Nn)
                    *(float2*)(out + ((size_t)b * Nn + nr1) * Nn + g) =
                        make_float2(p10, p11);
            }
        }
    }

    // quad-reduce row sums; per-half slots (rows shared by warps w and w+4)
    rs0 += __shfl_xor_sync(0xffffffffu, rs0, 1);
    rs0 += __shfl_xor_sync(0xffffffffu, rs0, 2);
    rs1 += __shfl_xor_sync(0xffffffffu, rs1, 1);
    rs1 += __shfl_xor_sync(0xffffffffu, rs1, 2);
    if ((lane & 3) == 0) {
        rsum[half * 64 + wrow + (lane >> 2)] = rs0;
        rsum[half * 64 + wrow + (lane >> 2) + 8] = rs1;
    }
    __syncthreads();

    // rescale: 64 rows x 125 float4
    for (int i4 = t; i4 < 64 * 125; i4 += 256) {
        int row = i4 / 125, c4 = i4 - row * 125;
        int n = n0 + row;
        if (n < Nn) {
            float inv = __fdividef(1.0f, rsum[row] + rsum[64 + row]);
            float4* po = (float4*)(out + ((size_t)b * Nn + n) * Nn) + c4;
            float4 p = *po;
            p.x *= inv; p.y *= inv; p.z *= inv; p.w *= inv;
            *po = p;
        }
    }
}

// ---------------------------------------------------------------------------
// Launch
// ---------------------------------------------------------------------------
extern "C" void kernel_launch(void* const* d_in, const int* in_sizes, int n_in,
                              void* d_out, int out_size) {
    const float* enc_nodes = (const float*)d_in[0];
    const float* enc_first = (const float*)d_in[1];
    const float* enc_last  = (const float*)d_in[2];
    const float* mask      = (const float*)d_in[3];
    const float* Wq_first  = (const float*)d_in[4];
    const float* Wq_last   = (const float*)d_in[5];
    const float* Wk        = (const float*)d_in[6];
    const float* Wv        = (const float*)d_in[7];
    const float* Wc        = (const float*)d_in[8];
    const float* bc        = (const float*)d_in[9];
    float* out = (float*)d_out;

    const int PROJ_SMEM = (64 * 128 + 128 * 132) * 4;   // 100352

    static int configured = 0;
    if (!configured) {
        cudaFuncSetAttribute(stageA_kernel,
            cudaFuncAttributeMaxDynamicSharedMemorySize, PROJ_SMEM);
        cudaFuncSetAttribute(attn_mma_kernel,
            cudaFuncAttributeMaxDynamicSharedMemorySize, ATT_SMEM);
        cudaFuncSetAttribute(combine_kernel,
            cudaFuncAttributeMaxDynamicSharedMemorySize, PROJ_SMEM);
        cudaFuncSetAttribute(pointer_mma_kernel,
            cudaFuncAttributeMaxDynamicSharedMemorySize, PTR_SMEM);
        configured = 1;
    }

    // A) q/k/v projections (split bf16) + maskbits + enc split
    stageA_kernel<<<1814, 256, PROJ_SMEM>>>(enc_nodes, enc_first, enc_last,
                                            mask, Wq_first, Wq_last, Wk, Wv);
    // B) attention via HMMA
    attn_mma_kernel<<<Bb * Hh * 4, 256, ATT_SMEM>>>();
    // C) combine -> mh split bf16
    combine_kernel<<<500, 256, PROJ_SMEM>>>(Wc, bc);
    // D) pointer attention via HMMA (512 blocks, 2/SM)
    pointer_mma_kernel<<<Bb * 8, 256, PTR_SMEM>>>(out);

    (void)in_sizes; (void)n_in; (void)out_size;
}

// round 7
// speedup vs baseline: 3.2828x; 1.1674x over previous
#include <cuda_runtime.h>
#include <cuda_bf16.h>
#include <math.h>

// ---------------------------------------------------------------------------
// POMO decoder v7 — all GEMMs on HMMA split-bf16 3-pass.
// B=64, N=500, E=128, H=8, D=16
// Pipeline: prep (splits+maskbits) -> qkv proj (HMMA) -> attn (HMMA)
//           -> combine (HMMA) -> pointer (HMMA).
// ---------------------------------------------------------------------------

#define Bb 64
#define Nn 500
#define Hh 8
#define QKV_STRIDE 40   // [hi 16 | lo 16 | pad 8] bf16 => 80B rows (LDSM clean)

typedef unsigned long long ull;

__device__ unsigned g_maskbits[Bb * Nn * 16];
// split bf16: q/k/v per (b,h): [512 rows][40], q pre-scaled by log2e/4
__device__ __nv_bfloat16 g_q_split[Bb * Hh * 512 * QKV_STRIDE];
__device__ __nv_bfloat16 g_k_split[Bb * Hh * 512 * QKV_STRIDE];
__device__ __nv_bfloat16 g_v_split[Bb * Hh * 512 * QKV_STRIDE];
// split bf16 row buffers: [b][row 512][hi 128 | lo 128]
__device__ __nv_bfloat16 g_enc_split[Bb * 512 * 256];
__device__ __nv_bfloat16 g_first_split[Bb * 512 * 256];
__device__ __nv_bfloat16 g_last_split[Bb * 512 * 256];
__device__ __nv_bfloat16 g_att_split[Bb * 512 * 256];
__device__ __nv_bfloat16 g_mh_split[Bb * 512 * 256];
// split weights: 5 x [f 128][hi 128 | lo 128]  (Wqf, Wql, Wk, Wv, Wc)
__device__ __nv_bfloat16 g_w_split[5 * 128 * 256];

__device__ __forceinline__ unsigned smem_u32(const void* p) {
    unsigned a;
    asm("{ .reg .u64 t; cvta.to.shared.u64 t, %1; cvt.u32.u64 %0, t; }"
        : "=r"(a) : "l"(p));
    return a;
}

// ---- mma.sync / ldmatrix helpers -------------------------------------------
__device__ __forceinline__ void ldmx4(unsigned* r, unsigned addr) {
    asm volatile(
        "ldmatrix.sync.aligned.m8n8.x4.shared.b16 {%0,%1,%2,%3}, [%4];"
        : "=r"(r[0]), "=r"(r[1]), "=r"(r[2]), "=r"(r[3]) : "r"(addr));
}
__device__ __forceinline__ void ldmx4t(unsigned* r, unsigned addr) {
    asm volatile(
        "ldmatrix.sync.aligned.m8n8.x4.trans.shared.b16 {%0,%1,%2,%3}, [%4];"
        : "=r"(r[0]), "=r"(r[1]), "=r"(r[2]), "=r"(r[3]) : "r"(addr));
}
__device__ __forceinline__ void mma16816(float* c, const unsigned* a,
                                         unsigned b0, unsigned b1) {
    asm volatile(
        "mma.sync.aligned.m16n8k16.row.col.f32.bf16.bf16.f32 "
        "{%0,%1,%2,%3}, {%4,%5,%6,%7}, {%8,%9}, {%0,%1,%2,%3};"
        : "+f"(c[0]), "+f"(c[1]), "+f"(c[2]), "+f"(c[3])
        : "r"(a[0]), "r"(a[1]), "r"(a[2]), "r"(a[3]), "r"(b0), "r"(b1));
}
__device__ __forceinline__ unsigned pack_bf2(float x, float y) {
    __nv_bfloat162 h = __floats2bfloat162_rn(x, y);
    return *(unsigned*)&h;
}

// ---------------------------------------------------------------------------
// Prep: split enc_nodes/enc_first/enc_last rows, split weights, maskbits.
// grid = 192 + 5 + 250 = 447 blocks x 256 threads.
// ---------------------------------------------------------------------------
__global__ void __launch_bounds__(256)
prep_kernel(const float* __restrict__ enc_nodes,
            const float* __restrict__ enc_first,
            const float* __restrict__ enc_last,
            const float* __restrict__ mask,
            const float* __restrict__ Wqf, const float* __restrict__ Wql,
            const float* __restrict__ Wk, const float* __restrict__ Wv,
            const float* __restrict__ Wc) {
    int bi = blockIdx.x;
    int t = threadIdx.x;
    if (bi < 192) {
        int grp = bi >> 6, b = bi & 63;
        const float* src3 = (grp == 0) ? enc_nodes
                           : (grp == 1) ? enc_first : enc_last;
        __nv_bfloat16* dst3 = (grp == 0) ? g_enc_split
                             : (grp == 1) ? g_first_split : g_last_split;
        const float4* src = (const float4*)(src3 + (size_t)b * Nn * 128);
        for (int i4 = t; i4 < Nn * 32; i4 += 256) {
            int n = i4 >> 5, e4 = i4 & 31;
            float4 v = src[i4];
            __nv_bfloat162 h01 = __floats2bfloat162_rn(v.x, v.y);
            __nv_bfloat162 h23 = __floats2bfloat162_rn(v.z, v.w);
            float2 hf01 = __bfloat1622float2(h01);
            float2 hf23 = __bfloat1622float2(h23);
            __nv_bfloat162 l01 =
                __floats2bfloat162_rn(v.x - hf01.x, v.y - hf01.y);
            __nv_bfloat162 l23 =
                __floats2bfloat162_rn(v.z - hf23.x, v.w - hf23.y);
            __nv_bfloat16* dst = dst3 + ((size_t)(b * 512 + n)) * 256 + e4 * 4;
            *(__nv_bfloat162*)(dst) = h01;
            *(__nv_bfloat162*)(dst + 2) = h23;
            *(__nv_bfloat162*)(dst + 128) = l01;
            *(__nv_bfloat162*)(dst + 130) = l23;
        }
    } else if (bi < 197) {
        int widx = bi - 192;
        const float* W = (widx == 0) ? Wqf : (widx == 1) ? Wql
                        : (widx == 2) ? Wk : (widx == 3) ? Wv : Wc;
        __nv_bfloat16* dst = g_w_split + widx * 32768;
        for (int i = t; i < 16384; i += 256) {
            int f = i >> 7, e = i & 127;
            float r = W[i];
            __nv_bfloat16 hi = __float2bfloat16(r);
            float lo = r - __bfloat162float(hi);
            dst[f * 256 + e] = hi;
            dst[f * 256 + 128 + e] = __float2bfloat16(lo);
        }
    } else {
        int wid = t >> 5, lane = t & 31;
        int rowbase = (bi - 197) * 128 + wid * 16;
        for (int rr = 0; rr < 16; ++rr) {
            int row = rowbase + rr;
            const float* mrow = mask + (size_t)row * Nn;
            unsigned* brow = g_maskbits + (size_t)row * 16;
            #pragma unroll
            for (int w = 0; w < 16; ++w) {
                int g = w * 32 + lane;
                float v = (g < Nn) ? mrow[g] : -1e9f;
                unsigned bal = __ballot_sync(0xffffffffu, v > -1.0f);
                if (lane == 0) brow[w] = bal;
            }
        }
    }
}

// ---------------------------------------------------------------------------
// HMMA projection body: out[m, f] = sum_e A[m,e] W[f,e] (3-pass split),
// optional second (A1,W1) accumulated, optional bias, output split bf16.
// Block: 64 rows x 128 cols x K=128. 8 warps: (w&3)=row stripe, (w>>2)=f half.
// smem: As 64x264 + Ws 128x264 bf16 = 101376 B.
// mode 0: heads layout (g_q/k/v_split, scale), mode 1: mh layout (+bias).
// ---------------------------------------------------------------------------
#define PRJ_SMEM ((64 + 128) * 264 * 2)

__device__ __forceinline__ void proj_mma_body(
    const __nv_bfloat16* __restrict__ A0s, const __nv_bfloat16* __restrict__ W0s,
    const __nv_bfloat16* __restrict__ A1s, const __nv_bfloat16* __restrict__ W1s,
    const float* __restrict__ bias, __nv_bfloat16* __restrict__ outb,
    float scale, int mode, int m0) {
    extern __shared__ char smem[];
    __nv_bfloat16* As = (__nv_bfloat16*)smem;          // [64][264]
    __nv_bfloat16* Ws = As + 64 * 264;                 // [128][264]

    const int t = threadIdx.x;
    const int w = t >> 5, lane = t & 31;
    const int wrow = (w & 3) * 16;
    const int half = w >> 2;

    float acc[8][4];
    #pragma unroll
    for (int i = 0; i < 8; ++i)
        acc[i][0] = acc[i][1] = acc[i][2] = acc[i][3] = 0.f;

    const int npass = (A1s != nullptr) ? 2 : 1;
    for (int p = 0; p < npass; ++p) {
        const __nv_bfloat16* Ap = p ? A1s : A0s;
        const __nv_bfloat16* Wp = p ? W1s : W0s;
        if (p) __syncthreads();
        // fill As (rows m0..m0+63, global m -> (b,n) padded addressing)
        #pragma unroll
        for (int k = 0; k < 8; ++k) {
            int i4 = t + 256 * k;
            int row = i4 >> 5, c8 = i4 & 31;
            int m = m0 + row;
            int bb = m / Nn, nn = m - bb * Nn;
            uint4 v = *((const uint4*)(Ap + ((size_t)(bb * 512 + nn)) * 256) +
                        c8);
            *(uint4*)(As + row * 264 + c8 * 8) = v;
        }
        // fill Ws (contiguous)
        #pragma unroll
        for (int k = 0; k < 16; ++k) {
            int i4 = t + 256 * k;
            int row = i4 >> 5, c8 = i4 & 31;
            uint4 v = ((const uint4*)Wp)[i4];
            *(uint4*)(Ws + row * 264 + c8 * 8) = v;
        }
        __syncthreads();

        // A fragments hi/lo
        unsigned af_hi[8][4], af_lo[8][4];
        {
            unsigned rowa = wrow + (lane & 15);
            unsigned colb = (lane >> 4) * 8;
            #pragma unroll
            for (int kk = 0; kk < 8; ++kk) {
                unsigned addr =
                    smem_u32(As + rowa * 264 + colb + kk * 16);
                ldmx4(af_hi[kk], addr);
                ldmx4(af_lo[kk], addr + 128 * 2);
            }
        }
        unsigned browb = half * 64 + (lane & 15);
        unsigned bcolb = (lane >> 4) * 8;
        #pragma unroll
        for (int kk = 0; kk < 8; ++kk) {
            #pragma unroll
            for (int np = 0; np < 4; ++np) {
                unsigned baddr = smem_u32(Ws + (np * 16 + browb) * 264 +
                                          bcolb + kk * 16);
                unsigned bh[4], bl[4];
                ldmx4(bh, baddr);
                ldmx4(bl, baddr + 128 * 2);
                mma16816(acc[2 * np],     af_hi[kk], bh[0], bh[2]);
                mma16816(acc[2 * np + 1], af_hi[kk], bh[1], bh[3]);
                mma16816(acc[2 * np],     af_hi[kk], bl[0], bl[2]);
                mma16816(acc[2 * np + 1], af_hi[kk], bl[1], bl[3]);
                mma16816(acc[2 * np],     af_lo[kk], bh[0], bh[2]);
                mma16816(acc[2 * np + 1], af_lo[kk], bh[1], bh[3]);
            }
        }
    }

    // epilogue: split bf16 out
    const int mr0 = m0 + wrow + (lane >> 2);
    const int mr1 = mr0 + 8;
    const int b0 = mr0 / Nn, n0v = mr0 - b0 * Nn;
    const int b1 = mr1 / Nn, n1v = mr1 - b1 * Nn;
    #pragma unroll
    for (int ntile = 0; ntile < 8; ++ntile) {
        int f = half * 64 + ntile * 8 + (lane & 3) * 2;
        float bb0 = 0.f, bb1 = 0.f;
        if (bias) { bb0 = bias[f]; bb1 = bias[f + 1]; }
        float r00 = (acc[ntile][0] + bb0) * scale;
        float r01 = (acc[ntile][1] + bb1) * scale;
        float r10 = (acc[ntile][2] + bb0) * scale;
        float r11 = (acc[ntile][3] + bb1) * scale;
        __nv_bfloat162 h0 = __floats2bfloat162_rn(r00, r01);
        float2 f0 = __bfloat1622float2(h0);
        unsigned lo0 = pack_bf2(r00 - f0.x, r01 - f0.y);
        __nv_bfloat162 h1 = __floats2bfloat162_rn(r10, r11);
        float2 f1 = __bfloat1622float2(h1);
        unsigned lo1 = pack_bf2(r10 - f1.x, r11 - f1.y);
        if (mode == 0) {
            int h = f >> 4, d = f & 15;
            size_t base0 =
                ((size_t)((b0 * Hh + h) * 512 + n0v)) * QKV_STRIDE + d;
            *(unsigned*)(outb + base0) = *(unsigned*)&h0;
            *(unsigned*)(outb + base0 + 16) = lo0;
            size_t base1 =
                ((size_t)((b1 * Hh + h) * 512 + n1v)) * QKV_STRIDE + d;
            *(unsigned*)(outb + base1) = *(unsigned*)&h1;
            *(unsigned*)(outb + base1 + 16) = lo1;
        } else {
            size_t base0 = ((size_t)(b0 * 512 + n0v)) * 256 + f;
            *(unsigned*)(outb + base0) = *(unsigned*)&h0;
            *(unsigned*)(outb + base0 + 128) = lo0;
            size_t base1 = ((size_t)(b1 * 512 + n1v)) * 256 + f;
            *(unsigned*)(outb + base1) = *(unsigned*)&h1;
            *(unsigned*)(outb + base1 + 128) = lo1;
        }
    }
}

__global__ void __launch_bounds__(256, 1)
qkv_mma_kernel() {
    const float QS = 1.4426950408889634f * 0.25f;  // log2e / sqrt(D)
    int bi = blockIdx.x;
    int which = bi / 500;
    int m0 = (bi - which * 500) * 64;
    if (which == 0)
        proj_mma_body(g_first_split, g_w_split, g_last_split,
                      g_w_split + 32768, nullptr, g_q_split, QS, 0, m0);
    else if (which == 1)
        proj_mma_body(g_enc_split, g_w_split + 2 * 32768, nullptr, nullptr,
                      nullptr, g_k_split, 1.0f, 0, m0);
    else
        proj_mma_body(g_enc_split, g_w_split + 3 * 32768, nullptr, nullptr,
                      nullptr, g_v_split, 1.0f, 0, m0);
}

__global__ void __launch_bounds__(256, 1)
combine_mma_kernel(const float* __restrict__ bc) {
    proj_mma_body(g_att_split, g_w_split + 4 * 32768, nullptr, nullptr, bc,
                  g_mh_split, 1.0f, 1, blockIdx.x * 64);
}

// ---------------------------------------------------------------------------
// Attention via HMMA (core unchanged; epilogue now writes split bf16)
// ---------------------------------------------------------------------------
#define ATT_SMEM ((128 + 512 + 512) * QKV_STRIDE * 2)

__global__ void __launch_bounds__(256, 2)
attn_mma_kernel() {
    extern __shared__ char smem[];
    __nv_bfloat16* Qs = (__nv_bfloat16*)smem;
    __nv_bfloat16* Ks = Qs + 128 * QKV_STRIDE;
    __nv_bfloat16* Vs = Ks + 512 * QKV_STRIDE;

    const int t = threadIdx.x;
    const int w = t >> 5, lane = t & 31;
    const int bi = blockIdx.x;
    const int bh = bi >> 2, qt = bi & 3;
    const int b = bh >> 3, h = bh & 7;
    const int q0 = qt * 128;

    {
        const uint4* qsrc =
            (const uint4*)(g_q_split + ((size_t)bh * 512 + q0) * QKV_STRIDE);
        #pragma unroll
        for (int k = 0; k < 3; ++k) {
            int i = t + 256 * k;
            if (i < 640) ((uint4*)Qs)[i] = qsrc[i];
        }
        const uint4* ksrc =
            (const uint4*)(g_k_split + (size_t)bh * 512 * QKV_STRIDE);
        #pragma unroll
        for (int k = 0; k < 10; ++k)
            ((uint4*)Ks)[t + 256 * k] = ksrc[t + 256 * k];
        const uint4* vsrc =
            (const uint4*)(g_v_split + (size_t)bh * 512 * QKV_STRIDE);
        #pragma unroll
        for (int k = 0; k < 10; ++k)
            ((uint4*)Vs)[t + 256 * k] = vsrc[t + 256 * k];
    }
    __syncthreads();

    unsigned aq_hi[4], aq_lo[4];
    {
        unsigned qaddr = smem_u32(Qs + (w * 16 + (lane & 15)) * QKV_STRIDE +
                                  (lane >> 4) * 8);
        ldmx4(aq_hi, qaddr);
        ldmx4(aq_lo, qaddr + 32);
    }

    float oacc[2][4];
    #pragma unroll
    for (int j = 0; j < 4; ++j) { oacc[0][j] = 0.f; oacc[1][j] = 0.f; }
    float rs0 = 0.f, rs1 = 0.f;

    const int nr0 = q0 + w * 16 + (lane >> 2);
    const int nr1 = nr0 + 8;
    const int nr0c = (nr0 < Nn) ? nr0 : 0;
    const int nr1c = (nr1 < Nn) ? nr1 : 0;

    for (int gt = 0; gt < 4; ++gt) {
        const int g0 = gt * 128;

        float sacc[16][4];
        #pragma unroll
        for (int i = 0; i < 16; ++i)
            sacc[i][0] = sacc[i][1] = sacc[i][2] = sacc[i][3] = 0.f;

        #pragma unroll
        for (int np = 0; np < 8; ++np) {
            unsigned ka = smem_u32(Ks + (g0 + np * 16 + (lane & 15)) *
                                            QKV_STRIDE +
                                   (lane >> 4) * 8);
            unsigned kh[4], kl[4];
            ldmx4(kh, ka);
            ldmx4(kl, ka + 32);
            mma16816(sacc[2 * np],     aq_hi, kh[0], kh[2]);
            mma16816(sacc[2 * np],     aq_hi, kl[0], kl[2]);
            mma16816(sacc[2 * np],     aq_lo, kh[0], kh[2]);
            mma16816(sacc[2 * np + 1], aq_hi, kh[1], kh[3]);
            mma16816(sacc[2 * np + 1], aq_hi, kl[1], kl[3]);
            mma16816(sacc[2 * np + 1], aq_lo, kh[1], kh[3]);
        }

        uint4 m0 = *(const uint4*)(g_maskbits + ((size_t)b * Nn + nr0c) * 16 +
                                   gt * 4);
        uint4 m1 = *(const uint4*)(g_maskbits + ((size_t)b * Nn + nr1c) * 16 +
                                   gt * 4);
        unsigned mw0[4] = {m0.x, m0.y, m0.z, m0.w};
        unsigned mw1[4] = {m1.x, m1.y, m1.z, m1.w};

        #pragma unroll
        for (int kk = 0; kk < 8; ++kk) {
            unsigned pf_hi[4], pf_lo[4];
            #pragma unroll
            for (int half = 0; half < 2; ++half) {
                int ntile = 2 * kk + half;
                unsigned w0 = mw0[ntile >> 2];
                unsigned w1 = mw1[ntile >> 2];
                int bitb = (ntile & 3) * 8 + (lane & 3) * 2;
                float p00 = exp2f(sacc[ntile][0]);
                float p01 = exp2f(sacc[ntile][1]);
                float p10 = exp2f(sacc[ntile][2]);
                float p11 = exp2f(sacc[ntile][3]);
                p00 = ((w0 >> bitb) & 1u) ? p00 : 0.f;
                p01 = ((w0 >> (bitb + 1)) & 1u) ? p01 : 0.f;
                p10 = ((w1 >> bitb) & 1u) ? p10 : 0.f;
                p11 = ((w1 >> (bitb + 1)) & 1u) ? p11 : 0.f;
                rs0 += p00 + p01;
                rs1 += p10 + p11;
                __nv_bfloat162 h0 = __floats2bfloat162_rn(p00, p01);
                __nv_bfloat162 h1 = __floats2bfloat162_rn(p10, p11);
                float2 hf0 = __bfloat1622float2(h0);
                float2 hf1 = __bfloat1622float2(h1);
                pf_hi[2 * half + 0] = *(unsigned*)&h0;
                pf_hi[2 * half + 1] = *(unsigned*)&h1;
                pf_lo[2 * half + 0] = pack_bf2(p00 - hf0.x, p01 - hf0.y);
                pf_lo[2 * half + 1] = pack_bf2(p10 - hf1.x, p11 - hf1.y);
            }
            unsigned va = smem_u32(Vs + (g0 + kk * 16 + (lane & 15)) *
                                            QKV_STRIDE +
                                   (lane >> 4) * 8);
            unsigned vh[4], vl[4];
            ldmx4t(vh, va);
            ldmx4t(vl, va + 32);
            mma16816(oacc[0], pf_hi, vh[0], vh[1]);
            mma16816(oacc[0], pf_hi, vl[0], vl[1]);
            mma16816(oacc[0], pf_lo, vh[0], vh[1]);
            mma16816(oacc[1], pf_hi, vh[2], vh[3]);
            mma16816(oacc[1], pf_hi, vl[2], vl[3]);
            mma16816(oacc[1], pf_lo, vh[2], vh[3]);
        }
    }

    rs0 += __shfl_xor_sync(0xffffffffu, rs0, 1);
    rs0 += __shfl_xor_sync(0xffffffffu, rs0, 2);
    rs1 += __shfl_xor_sync(0xffffffffu, rs1, 1);
    rs1 += __shfl_xor_sync(0xffffffffu, rs1, 2);
    float inv0 = __fdividef(1.0f, rs0);
    float inv1 = __fdividef(1.0f, rs1);

    const int d0 = (lane & 3) * 2;
    if (nr0 < Nn) {
        size_t base = ((size_t)(b * 512 + nr0)) * 256 + h * 16 + d0;
        float v0 = oacc[0][0] * inv0, v1 = oacc[0][1] * inv0;
        __nv_bfloat162 hh = __floats2bfloat162_rn(v0, v1);
        float2 hf = __bfloat1622float2(hh);
        *(unsigned*)(g_att_split + base) = *(unsigned*)&hh;
        *(unsigned*)(g_att_split + base + 128) =
            pack_bf2(v0 - hf.x, v1 - hf.y);
        v0 = oacc[1][0] * inv0; v1 = oacc[1][1] * inv0;
        hh = __floats2bfloat162_rn(v0, v1);
        hf = __bfloat1622float2(hh);
        *(unsigned*)(g_att_split + base + 8) = *(unsigned*)&hh;
        *(unsigned*)(g_att_split + base + 8 + 128) =
            pack_bf2(v0 - hf.x, v1 - hf.y);
    }
    if (nr1 < Nn) {
        size_t base = ((size_t)(b * 512 + nr1)) * 256 + h * 16 + d0;
        float v0 = oacc[0][2] * inv1, v1 = oacc[0][3] * inv1;
        __nv_bfloat162 hh = __floats2bfloat162_rn(v0, v1);
        float2 hf = __bfloat1622float2(hh);
        *(unsigned*)(g_att_split + base) = *(unsigned*)&hh;
        *(unsigned*)(g_att_split + base + 128) =
            pack_bf2(v0 - hf.x, v1 - hf.y);
        v0 = oacc[1][2] * inv1; v1 = oacc[1][3] * inv1;
        hh = __floats2bfloat162_rn(v0, v1);
        hf = __bfloat1622float2(hh);
        *(unsigned*)(g_att_split + base + 8) = *(unsigned*)&hh;
        *(unsigned*)(g_att_split + base + 8 + 128) =
            pack_bf2(v0 - hf.x, v1 - hf.y);
    }
}

// ---------------------------------------------------------------------------
// Pointer via HMMA (unchanged from v6)
// ---------------------------------------------------------------------------
#define AS_STRIDE 264
#define PTR_SMEM ((64 + 128) * AS_STRIDE * 2 + 512)

__global__ void __launch_bounds__(256, 2)
pointer_mma_kernel(float* __restrict__ out) {
    extern __shared__ char smem[];
    __nv_bfloat16* As = (__nv_bfloat16*)smem;                 // [64][264]
    __nv_bfloat16* Bs = As + 64 * AS_STRIDE;                  // [128][264]
    float* rsum = (float*)(Bs + 128 * AS_STRIDE);             // [2][64]

    const int t = threadIdx.x;
    const int w = t >> 5, lane = t & 31;
    const int b = blockIdx.x >> 3;
    const int nt = blockIdx.x & 7;
    const int n0 = nt * 64;
    const int wrow = (w & 3) * 16;
    const int half = w >> 2;

    {
        const uint4* src =
            (const uint4*)(g_mh_split + ((size_t)(b * 512 + n0)) * 256);
        #pragma unroll
        for (int k = 0; k < 8; ++k) {
            int i4 = t + 256 * k;
            int row = i4 >> 5, c8 = i4 & 31;
            *(uint4*)(As + row * AS_STRIDE + c8 * 8) = src[i4];
        }
    }
    __syncthreads();

    unsigned af_hi[8][4], af_lo[8][4];
    {
        unsigned rowa = wrow + (lane & 15);
        unsigned colbase = (lane >> 4) * 8;
        #pragma unroll
        for (int kk = 0; kk < 8; ++kk) {
            unsigned addr = smem_u32(As + rowa * AS_STRIDE + colbase + kk * 16);
            ldmx4(af_hi[kk], addr);
            ldmx4(af_lo[kk], addr + 128 * 2);
        }
    }

    const float C1 = 0.08838834764831845f * 2.0f * 1.4426950408889634f;
    const float C2 = 10.0f * 1.4426950408889634f;

    const int nr0 = n0 + wrow + (lane >> 2);
    const int nr1 = nr0 + 8;
    const int nr0c = (nr0 < Nn) ? nr0 : 0;
    const int nr1c = (nr1 < Nn) ? nr1 : 0;
    float rs0 = 0.f, rs1 = 0.f;

    for (int gt = 0; gt < 4; ++gt) {
        const int g0 = gt * 128;
        __syncthreads();
        {
            const uint4* src =
                (const uint4*)(g_enc_split + ((size_t)(b * 512 + g0)) * 256);
            #pragma unroll
            for (int k = 0; k < 16; ++k) {
                int i4 = t + 256 * k;
                int row = i4 >> 5, c8 = i4 & 31;
                *(uint4*)(Bs + row * AS_STRIDE + c8 * 8) = src[i4];
            }
        }
        __syncthreads();

        float acc[8][4];
        #pragma unroll
        for (int i = 0; i < 8; ++i)
            acc[i][0] = acc[i][1] = acc[i][2] = acc[i][3] = 0.f;

        unsigned browb = half * 64 + (lane & 15);
        unsigned bcolb = (lane >> 4) * 8;
        #pragma unroll
        for (int kk = 0; kk < 8; ++kk) {
            #pragma unroll
            for (int np = 0; np < 4; ++np) {
                unsigned baddr = smem_u32(Bs + (np * 16 + browb) * AS_STRIDE +
                                          bcolb + kk * 16);
                unsigned bh[4], bl[4];
                ldmx4(bh, baddr);
                ldmx4(bl, baddr + 128 * 2);
                mma16816(acc[2 * np],     af_hi[kk], bh[0], bh[2]);
                mma16816(acc[2 * np + 1], af_hi[kk], bh[1], bh[3]);
                mma16816(acc[2 * np],     af_hi[kk], bl[0], bl[2]);
                mma16816(acc[2 * np + 1], af_hi[kk], bl[1], bl[3]);
                mma16816(acc[2 * np],     af_lo[kk], bh[0], bh[2]);
                mma16816(acc[2 * np + 1], af_lo[kk], bh[1], bh[3]);
            }
        }

        uint4 m0 = *(const uint4*)(g_maskbits + ((size_t)b * Nn + nr0c) * 16 +
                                   gt * 4);
        uint4 m1 = *(const uint4*)(g_maskbits + ((size_t)b * Nn + nr1c) * 16 +
                                   gt * 4);
        unsigned mw0[4] = {m0.x, m0.y, m0.z, m0.w};
        unsigned mw1[4] = {m1.x, m1.y, m1.z, m1.w};

        #pragma unroll
        for (int ntile = 0; ntile < 8; ++ntile) {
            int widx = half * 2 + (ntile >> 2);
            unsigned w0 = mw0[widx];
            unsigned w1 = mw1[widx];
            int bitb = (ntile & 3) * 8 + (lane & 3) * 2;
            float p00, p01, p10, p11;
            {
                float u = exp2f(acc[ntile][0] * C1);
                p00 = exp2f(C2 * (1.0f - __fdividef(2.0f, u + 1.0f)));
            }
            {
                float u = exp2f(acc[ntile][1] * C1);
                p01 = exp2f(C2 * (1.0f - __fdividef(2.0f, u + 1.0f)));
            }
            {
                float u = exp2f(acc[ntile][2] * C1);
                p10 = exp2f(C2 * (1.0f - __fdividef(2.0f, u + 1.0f)));
            }
            {
                float u = exp2f(acc[ntile][3] * C1);
                p11 = exp2f(C2 * (1.0f - __fdividef(2.0f, u + 1.0f)));
            }
            p00 = ((w0 >> bitb) & 1u) ? p00 : 0.f;
            p01 = ((w0 >> (bitb + 1)) & 1u) ? p01 : 0.f;
            p10 = ((w1 >> bitb) & 1u) ? p10 : 0.f;
            p11 = ((w1 >> (bitb + 1)) & 1u) ? p11 : 0.f;
            rs0 += p00 + p01;
            rs1 += p10 + p11;
            int g = g0 + half * 64 + ntile * 8 + (lane & 3) * 2;
            if (g < Nn) {
                if (nr0 < Nn)
                    *(float2*)(out + ((size_t)b * Nn + nr0) * Nn + g) =
                        make_float2(p00, p01);
                if (nr1 < Nn)
                    *(float2*)(out + ((size_t)b * Nn + nr1) * Nn + g) =
                        make_float2(p10, p11);
            }
        }
    }

    rs0 += __shfl_xor_sync(0xffffffffu, rs0, 1);
    rs0 += __shfl_xor_sync(0xffffffffu, rs0, 2);
    rs1 += __shfl_xor_sync(0xffffffffu, rs1, 1);
    rs1 += __shfl_xor_sync(0xffffffffu, rs1, 2);
    if ((lane & 3) == 0) {
        rsum[half * 64 + wrow + (lane >> 2)] = rs0;
        rsum[half * 64 + wrow + (lane >> 2) + 8] = rs1;
    }
    __syncthreads();

    for (int i4 = t; i4 < 64 * 125; i4 += 256) {
        int row = i4 / 125, c4 = i4 - row * 125;
        int n = n0 + row;
        if (n < Nn) {
            float inv = __fdividef(1.0f, rsum[row] + rsum[64 + row]);
            float4* po = (float4*)(out + ((size_t)b * Nn + n) * Nn) + c4;
            float4 p = *po;
            p.x *= inv; p.y *= inv; p.z *= inv; p.w *= inv;
            *po = p;
        }
    }
}

// ---------------------------------------------------------------------------
// Launch
// ---------------------------------------------------------------------------
extern "C" void kernel_launch(void* const* d_in, const int* in_sizes, int n_in,
                              void* d_out, int out_size) {
    const float* enc_nodes = (const float*)d_in[0];
    const float* enc_first = (const float*)d_in[1];
    const float* enc_last  = (const float*)d_in[2];
    const float* mask      = (const float*)d_in[3];
    const float* Wq_first  = (const float*)d_in[4];
    const float* Wq_last   = (const float*)d_in[5];
    const float* Wk        = (const float*)d_in[6];
    const float* Wv        = (const float*)d_in[7];
    const float* Wc        = (const float*)d_in[8];
    const float* bc        = (const float*)d_in[9];
    float* out = (float*)d_out;

    static int configured = 0;
    if (!configured) {
        cudaFuncSetAttribute(qkv_mma_kernel,
            cudaFuncAttributeMaxDynamicSharedMemorySize, PRJ_SMEM);
        cudaFuncSetAttribute(combine_mma_kernel,
            cudaFuncAttributeMaxDynamicSharedMemorySize, PRJ_SMEM);
        cudaFuncSetAttribute(attn_mma_kernel,
            cudaFuncAttributeMaxDynamicSharedMemorySize, ATT_SMEM);
        cudaFuncSetAttribute(pointer_mma_kernel,
            cudaFuncAttributeMaxDynamicSharedMemorySize, PTR_SMEM);
        configured = 1;
    }

    // 1) prep: input/weight splits + maskbits
    prep_kernel<<<447, 256>>>(enc_nodes, enc_first, enc_last, mask,
                              Wq_first, Wq_last, Wk, Wv, Wc);
    // 2) q/k/v projections via HMMA
    qkv_mma_kernel<<<1500, 256, PRJ_SMEM>>>();
    // 3) attention via HMMA
    attn_mma_kernel<<<Bb * Hh * 4, 256, ATT_SMEM>>>();
    // 4) combine via HMMA
    combine_mma_kernel<<<500, 256, PRJ_SMEM>>>(bc);
    // 5) pointer attention via HMMA
    pointer_mma_kernel<<<Bb * 8, 256, PTR_SMEM>>>(out);

    (void)in_sizes; (void)n_in; (void)out_size;
}